// round 11
// baseline (speedup 1.0000x reference)
#include <cuda_runtime.h>
#include <math.h>
#include <stdint.h>

// Problem constants
#define Bc 16
#define Nc 1024
#define Hc 4
#define KVc 960
#define Dc 240            // KV/4, per-head K/V feature dim

#define SZ_BHND (Bc*Hc*Nc*Dc)   // 15,728,640

// ---------------- scratch (static device globals; no allocation) ----------
__device__ float g_KhT [SZ_BHND];           // [bh][240][1024]  (tf32-rounded, TRANSPOSED)
__device__ float g_Vh  [SZ_BHND];           // [bh][1024][240]  (tf32-rounded)
__device__ float g_Qh  [SZ_BHND];           // per-scale [bh][d][1024] (tf32-rounded)
__device__ float g_S   [Bc*Hc*Dc*Dc];       // per-scale [bh][d][240]
__device__ float g_ctx [SZ_BHND];           // per-scale [bh][d][1024] (tf32-rounded, coalesced)
__device__ float g_Wo  [348160];            // tf32-rounded Wo1..4 concatenated
__device__ float g_part[1024];              // per score-block partial (sum, sumsq)

// ---------------- helpers ----------------
__device__ __forceinline__ void cpasync16(uint32_t dst, const void* src, int sz) {
    asm volatile("cp.async.ca.shared.global [%0], [%1], 16, %2;\n"
                 :: "r"(dst), "l"(src), "r"(sz));
}
__device__ __forceinline__ void cpasync4(uint32_t dst, const void* src) {
    asm volatile("cp.async.ca.shared.global [%0], [%1], 4;\n"
                 :: "r"(dst), "l"(src));
}
__device__ __forceinline__ uint32_t f2tf(float f) {
    uint32_t r; asm("cvt.rna.tf32.f32 %0, %1;" : "=r"(r) : "f"(f)); return r;
}
__device__ __forceinline__ float rndtf(float f) { return __uint_as_float(f2tf(f)); }

template<bool CVT>
__device__ __forceinline__ uint32_t ldop(float v) {
    return CVT ? f2tf(v) : __float_as_uint(v);
}
__device__ __forceinline__ void mma_tf32(float* acc, const uint32_t* a, const uint32_t* b) {
    asm volatile("mma.sync.aligned.m16n8k8.row.col.f32.tf32.tf32.f32 "
                 "{%0,%1,%2,%3}, {%4,%5,%6,%7}, {%8,%9}, {%0,%1,%2,%3};\n"
                 : "+f"(acc[0]), "+f"(acc[1]), "+f"(acc[2]), "+f"(acc[3])
                 : "r"(a[0]), "r"(a[1]), "r"(a[2]), "r"(a[3]), "r"(b[0]), "r"(b[1]));
}
__device__ __forceinline__ void ldsm4(uint32_t* r, uint32_t addr) {
    asm volatile("ldmatrix.sync.aligned.m8n8.x4.shared.b16 {%0,%1,%2,%3}, [%4];\n"
                 : "=r"(r[0]), "=r"(r[1]), "=r"(r[2]), "=r"(r[3]) : "r"(addr));
}

// =======================================================================
// 64x64 GEMM body: 128 threads, BK=16, NT (B [Nn][K] K-contig).
// LDSM: ldmatrix fragment loads (requires pre-rounded tf32 operands).
// =======================================================================
template<bool SC, bool CVTA, bool CVTB, bool RND, bool LDSM>
__device__ __forceinline__
void gemm64_body(const float* __restrict__ A, const float* __restrict__ B, float* __restrict__ C,
                 int M, int Nn, int K, int lda, int ldb, int ldc, int ldcC,
                 int m0, int n0, float alpha)
{
    const int tid = threadIdx.x, lane = tid & 31, warp = tid >> 5;
    const int wm = warp >> 1, wn = warp & 1;
    const int g = lane >> 2, c4 = lane & 3;

    __shared__ float sA[2][64 * 20];
    __shared__ float sB[2][64 * 20];

    float acc[2][4][4] = {};

    const int ar = tid >> 1, ac = (tid & 1) * 8;

    auto fill = [&](int s, int k0) {
        const float* ap = A + (long)(m0 + ar) * lda + k0 + ac;
        int sa = (m0 + ar < M) ? 16 : 0;
        cpasync16((uint32_t)__cvta_generic_to_shared(&sA[s][ar * 20 + ac]),     ap,     sa);
        cpasync16((uint32_t)__cvta_generic_to_shared(&sA[s][ar * 20 + ac + 4]), ap + 4, sa);
        const float* bp = B + (long)(n0 + ar) * ldb + k0 + ac;
        int sb = (n0 + ar < Nn) ? 16 : 0;
        cpasync16((uint32_t)__cvta_generic_to_shared(&sB[s][ar * 20 + ac]),     bp,     sb);
        cpasync16((uint32_t)__cvta_generic_to_shared(&sB[s][ar * 20 + ac + 4]), bp + 4, sb);
    };

    const uint32_t sAb = (uint32_t)__cvta_generic_to_shared(sA);
    const uint32_t sBb = (uint32_t)__cvta_generic_to_shared(sB);
    const int a_row = wm * 32 + (lane & 15);
    const int a_kh  = (lane >> 4) * 4;
    const int b_row = wn * 32 + ((lane & 16) >> 1) + (lane & 7);
    const int b_kh  = ((lane >> 3) & 1) * 4;

    const int KT = K >> 4;
    fill(0, 0);
    asm volatile("cp.async.commit_group;\n");
    for (int kt = 0; kt < KT; kt++) {
        int cur = kt & 1;
        if (kt + 1 < KT) fill(cur ^ 1, (kt + 1) << 4);
        asm volatile("cp.async.commit_group;\n");
        asm volatile("cp.async.wait_group 1;\n");
        __syncthreads();
        if (LDSM) {
            const uint32_t aBase = sAb + (uint32_t)(cur * 64 * 20) * 4u;
            const uint32_t bBase = sBb + (uint32_t)(cur * 64 * 20) * 4u;
            #pragma unroll
            for (int ks = 0; ks < 16; ks += 8) {
                uint32_t af[2][4], bfr[2][4];
                #pragma unroll
                for (int fm = 0; fm < 2; fm++)
                    ldsm4(af[fm], aBase + (uint32_t)((a_row + fm * 16) * 20 + ks + a_kh) * 4u);
                #pragma unroll
                for (int fp = 0; fp < 2; fp++)
                    ldsm4(bfr[fp], bBase + (uint32_t)((b_row + fp * 16) * 20 + ks + b_kh) * 4u);
                #pragma unroll
                for (int fm = 0; fm < 2; fm++)
                    #pragma unroll
                    for (int fn = 0; fn < 4; fn++)
                        mma_tf32(acc[fm][fn], af[fm], &bfr[fn >> 1][(fn & 1) * 2]);
            }
        } else {
            const float* a_s = sA[cur];
            const float* b_s = sB[cur];
            #pragma unroll
            for (int ks = 0; ks < 16; ks += 8) {
                uint32_t af[2][4], bf[4][2];
                #pragma unroll
                for (int fm = 0; fm < 2; fm++) {
                    int mb = wm * 32 + fm * 16;
                    af[fm][0] = ldop<CVTA>(a_s[(mb + g    ) * 20 + ks + c4]);
                    af[fm][1] = ldop<CVTA>(a_s[(mb + g + 8) * 20 + ks + c4]);
                    af[fm][2] = ldop<CVTA>(a_s[(mb + g    ) * 20 + ks + c4 + 4]);
                    af[fm][3] = ldop<CVTA>(a_s[(mb + g + 8) * 20 + ks + c4 + 4]);
                }
                #pragma unroll
                for (int fn = 0; fn < 4; fn++) {
                    int nb = wn * 32 + fn * 8 + g;
                    bf[fn][0] = ldop<CVTB>(b_s[nb * 20 + ks + c4]);
                    bf[fn][1] = ldop<CVTB>(b_s[nb * 20 + ks + c4 + 4]);
                }
                #pragma unroll
                for (int fm = 0; fm < 2; fm++)
                    #pragma unroll
                    for (int fn = 0; fn < 4; fn++)
                        mma_tf32(acc[fm][fn], af[fm], bf[fn]);
            }
        }
        __syncthreads();
    }

    #pragma unroll
    for (int fm = 0; fm < 2; fm++) {
        int row0 = m0 + wm * 32 + fm * 16 + g;
        #pragma unroll
        for (int half = 0; half < 2; half++) {
            int r = row0 + half * 8;
            if (r >= M) continue;
            #pragma unroll
            for (int fn = 0; fn < 4; fn++) {
                int col = n0 + wn * 32 + fn * 8 + c4 * 2;
                if (col >= Nn) continue;
                float v0 = alpha * acc[fm][fn][half * 2 + 0];
                float v1 = alpha * acc[fm][fn][half * 2 + 1];
                if (RND) { v0 = rndtf(v0); v1 = rndtf(v1); }
                if (SC) {
                    C[(long)r * ldc + (long)col * ldcC] = v0;
                    C[(long)r * ldc + (long)(col + 1) * ldcC] = v1;
                } else {
                    *(float2*)(C + (long)r * ldc + col) = make_float2(v0, v1);
                }
            }
        }
    }
}

// All-scale Q projection: z = (sc<<6)|bh. Qh[sc][bh][e][n], rounded.
__global__ __launch_bounds__(128)
void qproj_all(const float* __restrict__ e1, const float* __restrict__ e2,
               const float* __restrict__ e3, const float* __restrict__ e4,
               const float* __restrict__ w1, const float* __restrict__ w2,
               const float* __restrict__ w3, const float* __restrict__ w4,
               float* __restrict__ Qh)
{
    const int z = blockIdx.z, sc = z >> 6, bh = z & 63, b = bh >> 2, h = bh & 3;
    const int d = 16 << sc, CH = d * 4;
    const int m0 = blockIdx.y * 64;
    if (m0 >= d) return;
    const float* emb = sc == 0 ? e1 : sc == 1 ? e2 : sc == 2 ? e3 : e4;
    const float* Wq  = sc == 0 ? w1 : sc == 1 ? w2 : sc == 2 ? w3 : w4;
    const float* A = Wq + (long)h * d * d;                 // [d][d]
    const float* B = emb + (long)b * 1024 * CH + h * d;    // [1024][CH]
    float*       C = Qh + 65536L * (d - 16) + (long)bh * d * 1024;  // [d][1024]
    gemm64_body<false, true, true, true, false>(A, B, C, d, 1024, d, d, CH, 1024, 1,
                                                m0, blockIdx.x * 64, 1.f);
}

// All-scale ctx GEMM: z = (sc<<6)|bh. ctx[sc][bh][dd][n], rounded, COALESCED.
__global__ __launch_bounds__(128)
void ctx_all(const float* __restrict__ S, const float* __restrict__ Vh,
             float* __restrict__ ctx)
{
    const int z = blockIdx.z, sc = z >> 6, bh = z & 63;
    const int d = 16 << sc;
    const int m0 = blockIdx.y * 64;
    if (m0 >= d) return;
    const float* A = S  + 15360L * (d - 16) + (long)bh * d * 240;   // [d][240]
    const float* B = Vh + (long)bh * 1024 * 240;                    // [1024][240]
    float*       C = ctx + 65536L * (d - 16) + (long)bh * d * 1024; // [d][1024]
    gemm64_body<false, false, false, true, true>(A, B, C, d, 1024, 240, 240, 240, 1024, 1,
                                                 m0, blockIdx.x * 64, 1.f);
}

// =======================================================================
// Fused gather + K/V projection (128x128 tile). Rounded outputs.
// Kh written TRANSPOSED: KhT[bh][c][n]; Vh written [bh][n][c].
// =======================================================================
__global__ __launch_bounds__(256)
void kvproj(const float* __restrict__ emb_all, const float* __restrict__ Wk,
            const float* __restrict__ Wv, float* __restrict__ KhT, float* __restrict__ Vh)
{
    const int m0 = blockIdx.y * 128, n0 = blockIdx.x * 128;
    const int tid = threadIdx.x, lane = tid & 31, warp = tid >> 5;
    const int wm = warp >> 1, wn = warp & 1;
    const int g = lane >> 2, c4 = lane & 3;

    __shared__ float sA[2][128 * 20];
    __shared__ float sB[2][128 * 20];

    float acc[2][8][4] = {};

    const int ar = tid >> 1, ac = (tid & 1) * 8;

    int m = m0 + ar;
    int b = m >> 12, h = (m >> 10) & 3, n = m & 1023;
    const float* abase = emb_all + ((long)(b * Nc + n)) * KVc;

    int r = n0 + ar;
    const float* bbase;
    int bsz;
    if (r < 240)      { bbase = Wk + (long)r * 240;         bsz = 16; }
    else if (r < 480) { bbase = Wv + (long)(r - 240) * 240; bsz = 16; }
    else              { bbase = Wk;                          bsz = 0; }

    auto seg = [&](int j) {
        return j < 16 ? 16 * h + j
             : j < 48 ? 64 + 32 * h + (j - 16)
             : j < 112 ? 192 + 64 * h + (j - 48)
             : 448 + 128 * h + (j - 112);
    };

    auto fill = [&](int s, int k0) {
        cpasync16((uint32_t)__cvta_generic_to_shared(&sA[s][ar * 20 + ac]),     abase + seg(k0 + ac),     16);
        cpasync16((uint32_t)__cvta_generic_to_shared(&sA[s][ar * 20 + ac + 4]), abase + seg(k0 + ac + 4), 16);
        cpasync16((uint32_t)__cvta_generic_to_shared(&sB[s][ar * 20 + ac]),     bbase + k0 + ac,          bsz);
        cpasync16((uint32_t)__cvta_generic_to_shared(&sB[s][ar * 20 + ac + 4]), bbase + k0 + ac + 4,      bsz);
    };

    const int KT = Dc >> 4;   // 15
    fill(0, 0);
    asm volatile("cp.async.commit_group;\n");
    for (int kt = 0; kt < KT; kt++) {
        int cur = kt & 1;
        if (kt + 1 < KT) fill(cur ^ 1, (kt + 1) << 4);
        asm volatile("cp.async.commit_group;\n");
        asm volatile("cp.async.wait_group 1;\n");
        __syncthreads();
        const float* a_s = sA[cur];
        const float* b_s = sB[cur];
        #pragma unroll
        for (int ks = 0; ks < 16; ks += 8) {
            uint32_t af[2][4], bf[8][2];
            #pragma unroll
            for (int fm = 0; fm < 2; fm++) {
                int mb = wm * 32 + fm * 16;
                af[fm][0] = f2tf(a_s[(mb + g    ) * 20 + ks + c4]);
                af[fm][1] = f2tf(a_s[(mb + g + 8) * 20 + ks + c4]);
                af[fm][2] = f2tf(a_s[(mb + g    ) * 20 + ks + c4 + 4]);
                af[fm][3] = f2tf(a_s[(mb + g + 8) * 20 + ks + c4 + 4]);
            }
            #pragma unroll
            for (int fn = 0; fn < 8; fn++) {
                int nb = wn * 64 + fn * 8 + g;
                bf[fn][0] = f2tf(b_s[nb * 20 + ks + c4]);
                bf[fn][1] = f2tf(b_s[nb * 20 + ks + c4 + 4]);
            }
            #pragma unroll
            for (int fm = 0; fm < 2; fm++)
                #pragma unroll
                for (int fn = 0; fn < 8; fn++)
                    mma_tf32(acc[fm][fn], af[fm], bf[fn]);
        }
        __syncthreads();
    }

    #pragma unroll
    for (int fm = 0; fm < 2; fm++) {
        int row0 = wm * 32 + fm * 16 + g;
        #pragma unroll
        for (int half = 0; half < 2; half++) {
            long rr = (long)(m0 + row0 + half * 8);
            int bh_o = (int)(rr >> 10), n_o = (int)(rr & 1023);
            #pragma unroll
            for (int fn = 0; fn < 8; fn++) {
                int col = n0 + wn * 64 + fn * 8 + c4 * 2;
                float2 v = make_float2(rndtf(acc[fm][fn][half * 2]),
                                       rndtf(acc[fm][fn][half * 2 + 1]));
                if (col < 240) {
                    float* p = KhT + ((long)bh_o * 240 + col) * 1024 + n_o;
                    p[0] = v.x; p[1024] = v.y;
                } else if (col < 480) {
                    *(float2*)(Vh + rr * 240 + col - 240) = v;
                }
            }
        }
    }
}

// =======================================================================
// All-scale score GEMM with ldmatrix + fused stats partials.
// =======================================================================
__global__ __launch_bounds__(256)
void score_all(const float* __restrict__ Qh, const float* __restrict__ KhT,
               float* __restrict__ S, float* __restrict__ part, float alpha)
{
    const int z = blockIdx.z, sc = z >> 6, bh = z & 63;
    const int d = 16 << sc;
    const int m0 = blockIdx.y * 64;
    if (m0 >= d) return;

    const float* A = Qh  + 65536L * (d - 16) + (long)bh * d * 1024;  // [d][1024]
    const float* B = KhT + (long)bh * 240 * 1024;                    // [240][1024]
    float*       C = S   + 15360L * (d - 16) + (long)bh * d * 240;   // [d][240]

    const int tid = threadIdx.x, lane = tid & 31, warp = tid >> 5;
    const int wm = warp >> 2, wn = warp & 3;      // 2 x 4 warps, warp tile 32 x 64
    const int g = lane >> 2, c4 = lane & 3;

    __shared__ float sA[2][64 * 20];
    __shared__ float sB[2][256 * 20];
    __shared__ float red[16];

    float acc[2][8][4] = {};

    const int lr = tid >> 2, lq = (tid & 3) * 4;

    auto fill = [&](int s, int k0) {
        cpasync16((uint32_t)__cvta_generic_to_shared(&sA[s][lr * 20 + lq]),
                  A + (long)(m0 + lr) * 1024 + k0 + lq, (m0 + lr < d) ? 16 : 0);
        #pragma unroll
        for (int rd = 0; rd < 4; rd++) {
            int row = lr + rd * 64;
            cpasync16((uint32_t)__cvta_generic_to_shared(&sB[s][row * 20 + lq]),
                      B + (long)row * 1024 + k0 + lq, (row < 240) ? 16 : 0);
        }
    };

    const uint32_t sAb = (uint32_t)__cvta_generic_to_shared(sA);
    const uint32_t sBb = (uint32_t)__cvta_generic_to_shared(sB);
    const int a_row = wm * 32 + (lane & 15);
    const int a_kh  = (lane >> 4) * 4;
    const int b_row = wn * 64 + ((lane & 16) >> 1) + (lane & 7);
    const int b_kh  = ((lane >> 3) & 1) * 4;

    const int KT = 64;   // K = 1024, BK = 16
    fill(0, 0);
    asm volatile("cp.async.commit_group;\n");
    for (int kt = 0; kt < KT; kt++) {
        int cur = kt & 1;
        if (kt + 1 < KT) fill(cur ^ 1, (kt + 1) << 4);
        asm volatile("cp.async.commit_group;\n");
        asm volatile("cp.async.wait_group 1;\n");
        __syncthreads();
        const uint32_t aBase = sAb + (uint32_t)(cur * 64 * 20) * 4u;
        const uint32_t bBase = sBb + (uint32_t)(cur * 256 * 20) * 4u;
        #pragma unroll
        for (int ks = 0; ks < 16; ks += 8) {
            uint32_t af[2][4], bfr[16];
            #pragma unroll
            for (int fm = 0; fm < 2; fm++)
                ldsm4(af[fm], aBase + (uint32_t)((a_row + fm * 16) * 20 + ks + a_kh) * 4u);
            #pragma unroll
            for (int fp = 0; fp < 4; fp++)
                ldsm4(&bfr[fp * 4], bBase + (uint32_t)((b_row + fp * 16) * 20 + ks + b_kh) * 4u);
            #pragma unroll
            for (int fm = 0; fm < 2; fm++)
                #pragma unroll
                for (int fn = 0; fn < 8; fn++)
                    mma_tf32(acc[fm][fn], af[fm], &bfr[(fn >> 1) * 4 + (fn & 1) * 2]);
        }
        __syncthreads();
    }

    float ls = 0.f, lss = 0.f;
    #pragma unroll
    for (int fm = 0; fm < 2; fm++) {
        int row0 = m0 + wm * 32 + fm * 16 + g;
        #pragma unroll
        for (int half = 0; half < 2; half++) {
            int r = row0 + half * 8;
            if (r >= d) continue;
            #pragma unroll
            for (int fn = 0; fn < 8; fn++) {
                int col = wn * 64 + fn * 8 + c4 * 2;
                if (col >= 240) continue;
                float v0 = alpha * acc[fm][fn][half * 2];
                float v1 = alpha * acc[fm][fn][half * 2 + 1];
                *(float2*)(C + (long)r * 240 + col) = make_float2(v0, v1);
                ls  += v0 + v1;
                lss += v0 * v0 + v1 * v1;
            }
        }
    }

    #pragma unroll
    for (int o = 16; o; o >>= 1) {
        ls  += __shfl_xor_sync(0xffffffffu, ls,  o);
        lss += __shfl_xor_sync(0xffffffffu, lss, o);
    }
    if (lane == 0) { red[warp] = ls; red[8 + warp] = lss; }
    __syncthreads();
    if (tid == 0) {
        float s = 0.f, ss = 0.f;
        #pragma unroll
        for (int j = 0; j < 8; j++) { s += red[j]; ss += red[8 + j]; }
        int idx = z * 2 + blockIdx.y;
        part[2 * idx]     = s;
        part[2 * idx + 1] = ss;
    }
}

// =======================================================================
// Softmax apply (with inline stats from partials): one warp per row.
// =======================================================================
__global__ __launch_bounds__(256)
void softmax_all(float* __restrict__ S, const float* __restrict__ part)
{
    int row = blockIdx.x * 8 + (threadIdx.x >> 5);
    int l = threadIdx.x & 31;
    int sc, loc;
    if (row < 1024)      { sc = 0; loc = row; }
    else if (row < 3072) { sc = 1; loc = row - 1024; }
    else if (row < 7168) { sc = 2; loc = row - 3072; }
    else                 { sc = 3; loc = row - 7168; }
    int d = 16 << sc, dc = d - 16;
    int bh = loc >> (4 + sc);
    float* p = S + 15360L * dc + (long)loc * 240;

    // stats from partials (same arithmetic as old stats_combine)
    int idx = (sc << 6) | bh;
    int nb = (d > 64) ? 2 : 1;
    float s = 0.f, ss = 0.f;
    for (int j = 0; j < nb; j++) {
        s  += part[2 * (idx * 2 + j)];
        ss += part[2 * (idx * 2 + j) + 1];
    }
    float count = (float)(d * 240);
    float mean = s / count;
    float var  = ss / count - mean * mean;
    float istd = rsqrtf(var + 1e-5f);

    float v[8];
    float mx = -1e30f;
    #pragma unroll
    for (int t = 0; t < 8; t++) {
        int k = l + t * 32;
        float x = (k < 240) ? (p[k] - mean) * istd : -1e30f;
        v[t] = x; mx = fmaxf(mx, x);
    }
    #pragma unroll
    for (int o = 16; o; o >>= 1) mx = fmaxf(mx, __shfl_xor_sync(0xffffffffu, mx, o));
    float se = 0.f;
    #pragma unroll
    for (int t = 0; t < 8; t++) {
        int k = l + t * 32;
        float e = (k < 240) ? __expf(v[t] - mx) : 0.f;
        v[t] = e; se += e;
    }
    #pragma unroll
    for (int o = 16; o; o >>= 1) se += __shfl_xor_sync(0xffffffffu, se, o);
    float inv = 1.f / se;
    #pragma unroll
    for (int t = 0; t < 8; t++) {
        int k = l + t * 32;
        if (k < 240) p[k] = rndtf(v[t] * inv);
    }
}

// Pre-round Wo weights to tf32 (bits identical to in-loop cvt).
__global__ void round_w(const float* __restrict__ w1, const float* __restrict__ w2,
                        const float* __restrict__ w3, const float* __restrict__ w4,
                        float* __restrict__ dst)
{
    int i = blockIdx.x * 256 + threadIdx.x;   // 0..348159
    const float* src; int off;
    if      (i < 4096)  { src = w1; off = i; }
    else if (i < 20480) { src = w2; off = i - 4096; }
    else if (i < 86016) { src = w3; off = i - 20480; }
    else                { src = w4; off = i - 86016; }
    dst[i] = rndtf(src[off]);
}

// =======================================================================
// Output projection, 128x128 tile, gathered A from ctx [bh][dd][n].
// A[m=(b,n)][c] = ctx[b*4 + (c&3)][c>>2][n]. B = pre-rounded Wo. LDSM loop.
// =======================================================================
__global__ __launch_bounds__(256)
void oproj128(const float* __restrict__ ctx, const float* __restrict__ Wo,
              float* __restrict__ Out, int d)
{
    const int CH = d * 4;
    const int m0 = blockIdx.y * 128, n0 = blockIdx.x * 128;
    const int tid = threadIdx.x, lane = tid & 31, warp = tid >> 5;
    const int wm = warp >> 1, wn = warp & 1;
    const int g = lane >> 2, c4 = lane & 3;

    __shared__ float sA[2][128 * 20];
    __shared__ float sB[2][128 * 20];

    float acc[2][8][4] = {};

    const int ar = tid >> 1, ac = (tid & 1) * 8;
    int m = m0 + ar, bb = m >> 10, nn = m & 1023;
    const float* abase = ctx + (long)bb * 4 * d * 1024 + nn;
    const float* bbase = Wo + (long)(n0 + ar) * CH;

    auto fill = [&](int s, int k0) {
        #pragma unroll
        for (int j = 0; j < 8; j++) {
            int c = k0 + ac + j, dd = c >> 2, h = c & 3;
            cpasync4((uint32_t)__cvta_generic_to_shared(&sA[s][ar * 20 + ac + j]),
                     abase + (long)(h * d + dd) * 1024);
        }
        cpasync16((uint32_t)__cvta_generic_to_shared(&sB[s][ar * 20 + ac]),     bbase + k0 + ac,     16);
        cpasync16((uint32_t)__cvta_generic_to_shared(&sB[s][ar * 20 + ac + 4]), bbase + k0 + ac + 4, 16);
    };

    const uint32_t sAb = (uint32_t)__cvta_generic_to_shared(sA);
    const uint32_t sBb = (uint32_t)__cvta_generic_to_shared(sB);
    const int a_row = wm * 32 + (lane & 15);
    const int a_kh  = (lane >> 4) * 4;
    const int b_row = wn * 64 + ((lane & 16) >> 1) + (lane & 7);
    const int b_kh  = ((lane >> 3) & 1) * 4;

    const int KT = CH >> 4;
    fill(0, 0);
    asm volatile("cp.async.commit_group;\n");
    for (int kt = 0; kt < KT; kt++) {
        int cur = kt & 1;
        if (kt + 1 < KT) fill(cur ^ 1, (kt + 1) << 4);
        asm volatile("cp.async.commit_group;\n");
        asm volatile("cp.async.wait_group 1;\n");
        __syncthreads();
        const uint32_t aBase = sAb + (uint32_t)(cur * 128 * 20) * 4u;
        const uint32_t bBase = sBb + (uint32_t)(cur * 128 * 20) * 4u;
        #pragma unroll
        for (int ks = 0; ks < 16; ks += 8) {
            uint32_t af[2][4], bfr[16];
            #pragma unroll
            for (int fm = 0; fm < 2; fm++)
                ldsm4(af[fm], aBase + (uint32_t)((a_row + fm * 16) * 20 + ks + a_kh) * 4u);
            #pragma unroll
            for (int fp = 0; fp < 4; fp++)
                ldsm4(&bfr[fp * 4], bBase + (uint32_t)((b_row + fp * 16) * 20 + ks + b_kh) * 4u);
            #pragma unroll
            for (int fm = 0; fm < 2; fm++)
                #pragma unroll
                for (int fn = 0; fn < 8; fn++)
                    mma_tf32(acc[fm][fn], af[fm], &bfr[(fn >> 1) * 4 + (fn & 1) * 2]);
        }
        __syncthreads();
    }

    #pragma unroll
    for (int fm = 0; fm < 2; fm++) {
        int row0 = m0 + wm * 32 + fm * 16 + g;
        #pragma unroll
        for (int half = 0; half < 2; half++) {
            int r = row0 + half * 8;
            #pragma unroll
            for (int fn = 0; fn < 8; fn++) {
                int col = n0 + wn * 64 + fn * 8 + c4 * 2;
                *(float2*)(Out + (long)r * CH + col) =
                    make_float2(acc[fm][fn][half * 2], acc[fm][fn][half * 2 + 1]);
            }
        }
    }
}

// Output projection, 64x64 tile (CH = 64 / 128), gathered A, LDSM loop.
__global__ __launch_bounds__(128)
void oproj64(const float* __restrict__ ctx, const float* __restrict__ Wo,
             float* __restrict__ Out, int d)
{
    const int CH = d * 4;
    const int m0 = blockIdx.y * 64, n0 = blockIdx.x * 64;
    const int tid = threadIdx.x, lane = tid & 31, warp = tid >> 5;
    const int wm = warp >> 1, wn = warp & 1;
    const int g = lane >> 2, c4 = lane & 3;

    __shared__ float sA[2][64 * 20];
    __shared__ float sB[2][64 * 20];

    float acc[2][4][4] = {};

    const int ar = tid >> 1, ac = (tid & 1) * 8;
    int m = m0 + ar, bb = m >> 10, nn = m & 1023;
    const float* abase = ctx + (long)bb * 4 * d * 1024 + nn;
    const float* bbase = Wo + (long)(n0 + ar) * CH;

    auto fill = [&](int s, int k0) {
        #pragma unroll
        for (int j = 0; j < 8; j++) {
            int c = k0 + ac + j, dd = c >> 2, h = c & 3;
            cpasync4((uint32_t)__cvta_generic_to_shared(&sA[s][ar * 20 + ac + j]),
                     abase + (long)(h * d + dd) * 1024);
        }
        cpasync16((uint32_t)__cvta_generic_to_shared(&sB[s][ar * 20 + ac]),     bbase + k0 + ac,     16);
        cpasync16((uint32_t)__cvta_generic_to_shared(&sB[s][ar * 20 + ac + 4]), bbase + k0 + ac + 4, 16);
    };

    const uint32_t sAb = (uint32_t)__cvta_generic_to_shared(sA);
    const uint32_t sBb = (uint32_t)__cvta_generic_to_shared(sB);
    const int a_row = wm * 32 + (lane & 15);
    const int a_kh  = (lane >> 4) * 4;
    const int b_row = wn * 32 + ((lane & 16) >> 1) + (lane & 7);
    const int b_kh  = ((lane >> 3) & 1) * 4;

    const int KT = CH >> 4;
    fill(0, 0);
    asm volatile("cp.async.commit_group;\n");
    for (int kt = 0; kt < KT; kt++) {
        int cur = kt & 1;
        if (kt + 1 < KT) fill(cur ^ 1, (kt + 1) << 4);
        asm volatile("cp.async.commit_group;\n");
        asm volatile("cp.async.wait_group 1;\n");
        __syncthreads();
        const uint32_t aBase = sAb + (uint32_t)(cur * 64 * 20) * 4u;
        const uint32_t bBase = sBb + (uint32_t)(cur * 64 * 20) * 4u;
        #pragma unroll
        for (int ks = 0; ks < 16; ks += 8) {
            uint32_t af[2][4], bfr[2][4];
            #pragma unroll
            for (int fm = 0; fm < 2; fm++)
                ldsm4(af[fm], aBase + (uint32_t)((a_row + fm * 16) * 20 + ks + a_kh) * 4u);
            #pragma unroll
            for (int fp = 0; fp < 2; fp++)
                ldsm4(bfr[fp], bBase + (uint32_t)((b_row + fp * 16) * 20 + ks + b_kh) * 4u);
            #pragma unroll
            for (int fm = 0; fm < 2; fm++)
                #pragma unroll
                for (int fn = 0; fn < 4; fn++)
                    mma_tf32(acc[fm][fn], af[fm], &bfr[fn >> 1][(fn & 1) * 2]);
        }
        __syncthreads();
    }

    #pragma unroll
    for (int fm = 0; fm < 2; fm++) {
        int row0 = m0 + wm * 32 + fm * 16 + g;
        #pragma unroll
        for (int half = 0; half < 2; half++) {
            int r = row0 + half * 8;
            #pragma unroll
            for (int fn = 0; fn < 4; fn++) {
                int col = n0 + wn * 32 + fn * 8 + c4 * 2;
                *(float2*)(Out + (long)r * CH + col) =
                    make_float2(acc[fm][fn][half * 2], acc[fm][fn][half * 2 + 1]);
            }
        }
    }
}

extern "C" void kernel_launch(void* const* d_in, const int* in_sizes, int n_in,
                              void* d_out, int out_size)
{
    const float* emb[4]  = { (const float*)d_in[0], (const float*)d_in[1],
                             (const float*)d_in[2], (const float*)d_in[3] };
    const float* emb_all = (const float*)d_in[4];
    const float* Wq[4]   = { (const float*)d_in[5], (const float*)d_in[6],
                             (const float*)d_in[7], (const float*)d_in[8] };
    const float* Wk      = (const float*)d_in[9];
    const float* Wv      = (const float*)d_in[10];
    const float* Wo[4]   = { (const float*)d_in[11], (const float*)d_in[12],
                             (const float*)d_in[13], (const float*)d_in[14] };
    float* out = (float*)d_out;

    float *pKhT, *pVh, *pQh, *pS, *pCtx, *pWo, *pPart;
    cudaGetSymbolAddress((void**)&pKhT,  g_KhT);
    cudaGetSymbolAddress((void**)&pVh,   g_Vh);
    cudaGetSymbolAddress((void**)&pQh,   g_Qh);
    cudaGetSymbolAddress((void**)&pS,    g_S);
    cudaGetSymbolAddress((void**)&pCtx,  g_ctx);
    cudaGetSymbolAddress((void**)&pWo,   g_Wo);
    cudaGetSymbolAddress((void**)&pPart, g_part);

    // 0) pre-round Wo weights
    round_w<<<1360, 256>>>(Wo[0], Wo[1], Wo[2], Wo[3], pWo);

    // 1) fused gather + K/V projection (Kh transposed)
    kvproj<<<dim3(4, 512), 256>>>(emb_all, Wk, Wv, pKhT, pVh);

    // 2) all Q projections, one launch
    qproj_all<<<dim3(16, 2, 256), 128>>>(emb[0], emb[1], emb[2], emb[3],
                                         Wq[0], Wq[1], Wq[2], Wq[3], pQh);

    const float alpha = 1.f / sqrtf((float)KVc);

    // 3) all score GEMMs, one launch (ldmatrix + fused stats partials)
    score_all<<<dim3(1, 2, 256), 256>>>(pQh, pKhT, pS, pPart, alpha);

    // 4) softmax (stats computed inline from partials)
    softmax_all<<<15360 / 8, 256>>>(pS, pPart);

    // 5) all ctx GEMMs, one launch (ldmatrix, coalesced [bh][dd][n] store)
    ctx_all<<<dim3(16, 2, 256), 128>>>(pS, pVh, pCtx);

    // 6) output projections (gathered A, pre-rounded Wo, ldmatrix)
    const long ctxOff[4] = {0, 65536L * 16, 65536L * 48, 65536L * 112};
    const int  woOff[4]  = {0, 4096, 20480, 86016};
    const int  chcum[4]  = {0, 64, 192, 448};
    oproj64 <<<dim3(1, 256), 128>>>(pCtx + ctxOff[0], pWo + woOff[0],
                                    out + 16384L * chcum[0], 16);
    oproj64 <<<dim3(2, 256), 128>>>(pCtx + ctxOff[1], pWo + woOff[1],
                                    out + 16384L * chcum[1], 32);
    oproj128<<<dim3(2, 128), 256>>>(pCtx + ctxOff[2], pWo + woOff[2],
                                    out + 16384L * chcum[2], 64);
    oproj128<<<dim3(4, 128), 256>>>(pCtx + ctxOff[3], pWo + woOff[3],
                                    out + 16384L * chcum[3], 128);
}

// round 12
// speedup vs baseline: 1.0132x; 1.0132x over previous
#include <cuda_runtime.h>
#include <math.h>
#include <stdint.h>

// Problem constants
#define Bc 16
#define Nc 1024
#define Hc 4
#define KVc 960
#define Dc 240            // KV/4, per-head K/V feature dim

#define SZ_BHND (Bc*Hc*Nc*Dc)   // 15,728,640

// ---------------- scratch (static device globals; no allocation) ----------
__device__ float g_KhT [SZ_BHND];           // [bh][240][1024]  (tf32-rounded, TRANSPOSED)
__device__ float g_Vh  [SZ_BHND];           // [bh][1024][240]  (tf32-rounded)
__device__ float g_Qh  [SZ_BHND];           // per-scale [bh][d][1024] (tf32-rounded)
__device__ float g_S   [Bc*Hc*Dc*Dc];       // per-scale [bh][d][240]
__device__ float g_ctxT[Bc*Nc*KVc];         // per-scale [B,N,CH]   (tf32-rounded)
__device__ float g_part[1024];              // per score-block partial (sum, sumsq)

// ---------------- helpers ----------------
__device__ __forceinline__ void cpasync16(uint32_t dst, const void* src, int sz) {
    asm volatile("cp.async.ca.shared.global [%0], [%1], 16, %2;\n"
                 :: "r"(dst), "l"(src), "r"(sz));
}
__device__ __forceinline__ uint32_t f2tf(float f) {
    uint32_t r; asm("cvt.rna.tf32.f32 %0, %1;" : "=r"(r) : "f"(f)); return r;
}
__device__ __forceinline__ float rndtf(float f) { return __uint_as_float(f2tf(f)); }

template<bool CVT>
__device__ __forceinline__ uint32_t ldop(float v) {
    return CVT ? f2tf(v) : __float_as_uint(v);
}
__device__ __forceinline__ void mma_tf32(float* acc, const uint32_t* a, const uint32_t* b) {
    asm volatile("mma.sync.aligned.m16n8k8.row.col.f32.tf32.tf32.f32 "
                 "{%0,%1,%2,%3}, {%4,%5,%6,%7}, {%8,%9}, {%0,%1,%2,%3};\n"
                 : "+f"(acc[0]), "+f"(acc[1]), "+f"(acc[2]), "+f"(acc[3])
                 : "r"(a[0]), "r"(a[1]), "r"(a[2]), "r"(a[3]), "r"(b[0]), "r"(b[1]));
}
__device__ __forceinline__ void ldsm4(uint32_t* r, uint32_t addr) {
    asm volatile("ldmatrix.sync.aligned.m8n8.x4.shared.b16 {%0,%1,%2,%3}, [%4];\n"
                 : "=r"(r[0]), "=r"(r[1]), "=r"(r[2]), "=r"(r[3]) : "r"(addr));
}

// =======================================================================
// Shared 64x64 GEMM body: 128 threads, BK=16, NT (B [Nn][K] K-contig).
// =======================================================================
template<bool SC, bool CVTA, bool CVTB, bool RND>
__device__ __forceinline__
void gemm64_body(const float* __restrict__ A, const float* __restrict__ B, float* __restrict__ C,
                 int M, int Nn, int K, int lda, int ldb, int ldc, int ldcC,
                 int m0, int n0, float alpha)
{
    const int tid = threadIdx.x, lane = tid & 31, warp = tid >> 5;
    const int wm = warp >> 1, wn = warp & 1;
    const int g = lane >> 2, c4 = lane & 3;

    __shared__ float sA[2][64 * 20];
    __shared__ float sB[2][64 * 20];

    float acc[2][4][4] = {};

    const int ar = tid >> 1, ac = (tid & 1) * 8;

    auto fill = [&](int s, int k0) {
        const float* ap = A + (long)(m0 + ar) * lda + k0 + ac;
        int sa = (m0 + ar < M) ? 16 : 0;
        cpasync16((uint32_t)__cvta_generic_to_shared(&sA[s][ar * 20 + ac]),     ap,     sa);
        cpasync16((uint32_t)__cvta_generic_to_shared(&sA[s][ar * 20 + ac + 4]), ap + 4, sa);
        const float* bp = B + (long)(n0 + ar) * ldb + k0 + ac;
        int sb = (n0 + ar < Nn) ? 16 : 0;
        cpasync16((uint32_t)__cvta_generic_to_shared(&sB[s][ar * 20 + ac]),     bp,     sb);
        cpasync16((uint32_t)__cvta_generic_to_shared(&sB[s][ar * 20 + ac + 4]), bp + 4, sb);
    };

    const int KT = K >> 4;
    fill(0, 0);
    asm volatile("cp.async.commit_group;\n");
    for (int kt = 0; kt < KT; kt++) {
        int cur = kt & 1;
        if (kt + 1 < KT) fill(cur ^ 1, (kt + 1) << 4);
        asm volatile("cp.async.commit_group;\n");
        asm volatile("cp.async.wait_group 1;\n");
        __syncthreads();
        const float* a_s = sA[cur];
        const float* b_s = sB[cur];
        #pragma unroll
        for (int ks = 0; ks < 16; ks += 8) {
            uint32_t af[2][4], bf[4][2];
            #pragma unroll
            for (int fm = 0; fm < 2; fm++) {
                int mb = wm * 32 + fm * 16;
                af[fm][0] = ldop<CVTA>(a_s[(mb + g    ) * 20 + ks + c4]);
                af[fm][1] = ldop<CVTA>(a_s[(mb + g + 8) * 20 + ks + c4]);
                af[fm][2] = ldop<CVTA>(a_s[(mb + g    ) * 20 + ks + c4 + 4]);
                af[fm][3] = ldop<CVTA>(a_s[(mb + g + 8) * 20 + ks + c4 + 4]);
            }
            #pragma unroll
            for (int fn = 0; fn < 4; fn++) {
                int nb = wn * 32 + fn * 8 + g;
                bf[fn][0] = ldop<CVTB>(b_s[nb * 20 + ks + c4]);
                bf[fn][1] = ldop<CVTB>(b_s[nb * 20 + ks + c4 + 4]);
            }
            #pragma unroll
            for (int fm = 0; fm < 2; fm++)
                #pragma unroll
                for (int fn = 0; fn < 4; fn++)
                    mma_tf32(acc[fm][fn], af[fm], bf[fn]);
        }
        __syncthreads();
    }

    #pragma unroll
    for (int fm = 0; fm < 2; fm++) {
        int row0 = m0 + wm * 32 + fm * 16 + g;
        #pragma unroll
        for (int half = 0; half < 2; half++) {
            int r = row0 + half * 8;
            if (r >= M) continue;
            #pragma unroll
            for (int fn = 0; fn < 4; fn++) {
                int col = n0 + wn * 32 + fn * 8 + c4 * 2;
                if (col >= Nn) continue;
                float v0 = alpha * acc[fm][fn][half * 2 + 0];
                float v1 = alpha * acc[fm][fn][half * 2 + 1];
                if (RND) { v0 = rndtf(v0); v1 = rndtf(v1); }
                if (SC) {
                    C[(long)r * ldc + (long)col * ldcC] = v0;
                    C[(long)r * ldc + (long)(col + 1) * ldcC] = v1;
                } else {
                    *(float2*)(C + (long)r * ldc + col) = make_float2(v0, v1);
                }
            }
        }
    }
}

// Generic 64x64 kernel (used for out-proj CH=64/128)
template<bool SC, bool CVTA, bool CVTB, bool RND>
__global__ __launch_bounds__(128)
void gemm64(const float* __restrict__ A, const float* __restrict__ B, float* __restrict__ C,
            int M, int Nn, int K, int lda, int ldb, int ldc, int ldcC, int Hs,
            long aB, long aH, long bB, long bH, long cB, long cH, float alpha)
{
    int z = blockIdx.z, zb = z / Hs, zh = z - zb * Hs;
    gemm64_body<SC, CVTA, CVTB, RND>(A + zb * aB + zh * aH, B + zb * bB + zh * bH,
                                     C + zb * cB + zh * cH,
                                     M, Nn, K, lda, ldb, ldc, ldcC,
                                     blockIdx.y * 64, blockIdx.x * 64, alpha);
}

// All-scale Q projection: z = (sc<<6)|bh. Qh[sc][bh][e][n], rounded.
__global__ __launch_bounds__(128)
void qproj_all(const float* __restrict__ e1, const float* __restrict__ e2,
               const float* __restrict__ e3, const float* __restrict__ e4,
               const float* __restrict__ w1, const float* __restrict__ w2,
               const float* __restrict__ w3, const float* __restrict__ w4,
               float* __restrict__ Qh)
{
    const int z = blockIdx.z, sc = z >> 6, bh = z & 63, b = bh >> 2, h = bh & 3;
    const int d = 16 << sc, CH = d * 4;
    const int m0 = blockIdx.y * 64;
    if (m0 >= d) return;
    const float* emb = sc == 0 ? e1 : sc == 1 ? e2 : sc == 2 ? e3 : e4;
    const float* Wq  = sc == 0 ? w1 : sc == 1 ? w2 : sc == 2 ? w3 : w4;
    const float* A = Wq + (long)h * d * d;                 // [d][d]
    const float* B = emb + (long)b * 1024 * CH + h * d;    // [1024][CH]
    float*       C = Qh + 65536L * (d - 16) + (long)bh * d * 1024;  // [d][1024]
    gemm64_body<false, true, true, true>(A, B, C, d, 1024, d, d, CH, 1024, 1,
                                         m0, blockIdx.x * 64, 1.f);
}

// All-scale ctx GEMM: z = (sc<<6)|bh. ctxT[b][n][dd*H+h], rounded.
__global__ __launch_bounds__(128)
void ctx_all(const float* __restrict__ S, const float* __restrict__ Vh,
             float* __restrict__ ctxT)
{
    const int z = blockIdx.z, sc = z >> 6, bh = z & 63, b = bh >> 2, h = bh & 3;
    const int d = 16 << sc, CH = d * 4;
    const int m0 = blockIdx.y * 64;
    if (m0 >= d) return;
    const float* A = S  + 15360L * (d - 16) + (long)bh * d * 240;   // [d][240]
    const float* B = Vh + (long)bh * 1024 * 240;                    // [1024][240]
    float*       C = ctxT + 65536L * (d - 16) + (long)b * 1024 * CH + h;
    gemm64_body<true, false, false, true>(A, B, C, d, 1024, 240, 240, 240, Hc, CH,
                                          m0, blockIdx.x * 64, 1.f);
}

// =======================================================================
// 128x128 tile, 256 threads, BK=16 — NT: C = alpha*A*B^T
// =======================================================================
template<bool CVTA, bool CVTB>
__global__ __launch_bounds__(256)
void gemm128(const float* __restrict__ A, const float* __restrict__ B, float* __restrict__ C,
             int M, int Nn, int K, int lda, int ldb, int ldc, float alpha)
{
    const int m0 = blockIdx.y * 128, n0 = blockIdx.x * 128;
    const int tid = threadIdx.x, lane = tid & 31, warp = tid >> 5;
    const int wm = warp >> 1, wn = warp & 1;   // 4x2 warps: warp tile 32x64
    const int g = lane >> 2, c4 = lane & 3;

    __shared__ float sA[2][128 * 20];
    __shared__ float sB[2][128 * 20];

    float acc[2][8][4] = {};

    const int ar = tid >> 1, ac = (tid & 1) * 8;

    auto fill = [&](int s, int k0) {
        const float* ap = A + (long)(m0 + ar) * lda + k0 + ac;
        int sa = (m0 + ar < M) ? 16 : 0;
        cpasync16((uint32_t)__cvta_generic_to_shared(&sA[s][ar * 20 + ac]),     ap,     sa);
        cpasync16((uint32_t)__cvta_generic_to_shared(&sA[s][ar * 20 + ac + 4]), ap + 4, sa);
        const float* bp = B + (long)(n0 + ar) * ldb + k0 + ac;
        int sb = (n0 + ar < Nn) ? 16 : 0;
        cpasync16((uint32_t)__cvta_generic_to_shared(&sB[s][ar * 20 + ac]),     bp,     sb);
        cpasync16((uint32_t)__cvta_generic_to_shared(&sB[s][ar * 20 + ac + 4]), bp + 4, sb);
    };

    const int KT = K >> 4;
    fill(0, 0);
    asm volatile("cp.async.commit_group;\n");
    for (int kt = 0; kt < KT; kt++) {
        int cur = kt & 1;
        if (kt + 1 < KT) fill(cur ^ 1, (kt + 1) << 4);
        asm volatile("cp.async.commit_group;\n");
        asm volatile("cp.async.wait_group 1;\n");
        __syncthreads();
        const float* a_s = sA[cur];
        const float* b_s = sB[cur];
        #pragma unroll
        for (int ks = 0; ks < 16; ks += 8) {
            uint32_t af[2][4], bf[8][2];
            #pragma unroll
            for (int fm = 0; fm < 2; fm++) {
                int mb = wm * 32 + fm * 16;
                af[fm][0] = ldop<CVTA>(a_s[(mb + g    ) * 20 + ks + c4]);
                af[fm][1] = ldop<CVTA>(a_s[(mb + g + 8) * 20 + ks + c4]);
                af[fm][2] = ldop<CVTA>(a_s[(mb + g    ) * 20 + ks + c4 + 4]);
                af[fm][3] = ldop<CVTA>(a_s[(mb + g + 8) * 20 + ks + c4 + 4]);
            }
            #pragma unroll
            for (int fn = 0; fn < 8; fn++) {
                int nb = wn * 64 + fn * 8 + g;
                bf[fn][0] = ldop<CVTB>(b_s[nb * 20 + ks + c4]);
                bf[fn][1] = ldop<CVTB>(b_s[nb * 20 + ks + c4 + 4]);
            }
            #pragma unroll
            for (int fm = 0; fm < 2; fm++)
                #pragma unroll
                for (int fn = 0; fn < 8; fn++)
                    mma_tf32(acc[fm][fn], af[fm], bf[fn]);
        }
        __syncthreads();
    }

    #pragma unroll
    for (int fm = 0; fm < 2; fm++) {
        int row0 = m0 + wm * 32 + fm * 16 + g;
        #pragma unroll
        for (int half = 0; half < 2; half++) {
            int r = row0 + half * 8;
            if (r >= M) continue;
            #pragma unroll
            for (int fn = 0; fn < 8; fn++) {
                int col = n0 + wn * 64 + fn * 8 + c4 * 2;
                if (col >= Nn) continue;
                *(float2*)(C + (long)r * ldc + col) =
                    make_float2(alpha * acc[fm][fn][half * 2], alpha * acc[fm][fn][half * 2 + 1]);
            }
        }
    }
}

// =======================================================================
// Fused gather + K/V projection (128x128 tile). Rounded outputs.
// Kh written TRANSPOSED: KhT[bh][c][n]; Vh written [bh][n][c].
// =======================================================================
__global__ __launch_bounds__(256)
void kvproj(const float* __restrict__ emb_all, const float* __restrict__ Wk,
            const float* __restrict__ Wv, float* __restrict__ KhT, float* __restrict__ Vh)
{
    const int m0 = blockIdx.y * 128, n0 = blockIdx.x * 128;
    const int tid = threadIdx.x, lane = tid & 31, warp = tid >> 5;
    const int wm = warp >> 1, wn = warp & 1;
    const int g = lane >> 2, c4 = lane & 3;

    __shared__ float sA[2][128 * 20];
    __shared__ float sB[2][128 * 20];

    float acc[2][8][4] = {};

    const int ar = tid >> 1, ac = (tid & 1) * 8;

    int m = m0 + ar;
    int b = m >> 12, h = (m >> 10) & 3, n = m & 1023;
    const float* abase = emb_all + ((long)(b * Nc + n)) * KVc;

    int r = n0 + ar;
    const float* bbase;
    int bsz;
    if (r < 240)      { bbase = Wk + (long)r * 240;         bsz = 16; }
    else if (r < 480) { bbase = Wv + (long)(r - 240) * 240; bsz = 16; }
    else              { bbase = Wk;                          bsz = 0; }

    auto seg = [&](int j) {
        return j < 16 ? 16 * h + j
             : j < 48 ? 64 + 32 * h + (j - 16)
             : j < 112 ? 192 + 64 * h + (j - 48)
             : 448 + 128 * h + (j - 112);
    };

    auto fill = [&](int s, int k0) {
        cpasync16((uint32_t)__cvta_generic_to_shared(&sA[s][ar * 20 + ac]),     abase + seg(k0 + ac),     16);
        cpasync16((uint32_t)__cvta_generic_to_shared(&sA[s][ar * 20 + ac + 4]), abase + seg(k0 + ac + 4), 16);
        cpasync16((uint32_t)__cvta_generic_to_shared(&sB[s][ar * 20 + ac]),     bbase + k0 + ac,          bsz);
        cpasync16((uint32_t)__cvta_generic_to_shared(&sB[s][ar * 20 + ac + 4]), bbase + k0 + ac + 4,      bsz);
    };

    const int KT = Dc >> 4;   // 15
    fill(0, 0);
    asm volatile("cp.async.commit_group;\n");
    for (int kt = 0; kt < KT; kt++) {
        int cur = kt & 1;
        if (kt + 1 < KT) fill(cur ^ 1, (kt + 1) << 4);
        asm volatile("cp.async.commit_group;\n");
        asm volatile("cp.async.wait_group 1;\n");
        __syncthreads();
        const float* a_s = sA[cur];
        const float* b_s = sB[cur];
        #pragma unroll
        for (int ks = 0; ks < 16; ks += 8) {
            uint32_t af[2][4], bf[8][2];
            #pragma unroll
            for (int fm = 0; fm < 2; fm++) {
                int mb = wm * 32 + fm * 16;
                af[fm][0] = f2tf(a_s[(mb + g    ) * 20 + ks + c4]);
                af[fm][1] = f2tf(a_s[(mb + g + 8) * 20 + ks + c4]);
                af[fm][2] = f2tf(a_s[(mb + g    ) * 20 + ks + c4 + 4]);
                af[fm][3] = f2tf(a_s[(mb + g + 8) * 20 + ks + c4 + 4]);
            }
            #pragma unroll
            for (int fn = 0; fn < 8; fn++) {
                int nb = wn * 64 + fn * 8 + g;
                bf[fn][0] = f2tf(b_s[nb * 20 + ks + c4]);
                bf[fn][1] = f2tf(b_s[nb * 20 + ks + c4 + 4]);
            }
            #pragma unroll
            for (int fm = 0; fm < 2; fm++)
                #pragma unroll
                for (int fn = 0; fn < 8; fn++)
                    mma_tf32(acc[fm][fn], af[fm], bf[fn]);
        }
        __syncthreads();
    }

    #pragma unroll
    for (int fm = 0; fm < 2; fm++) {
        int row0 = wm * 32 + fm * 16 + g;
        #pragma unroll
        for (int half = 0; half < 2; half++) {
            long rr = (long)(m0 + row0 + half * 8);
            int bh_o = (int)(rr >> 10), n_o = (int)(rr & 1023);
            #pragma unroll
            for (int fn = 0; fn < 8; fn++) {
                int col = n0 + wn * 64 + fn * 8 + c4 * 2;
                float2 v = make_float2(rndtf(acc[fm][fn][half * 2]),
                                       rndtf(acc[fm][fn][half * 2 + 1]));
                if (col < 240) {
                    float* p = KhT + ((long)bh_o * 240 + col) * 1024 + n_o;
                    p[0] = v.x; p[1024] = v.y;
                } else if (col < 480) {
                    *(float2*)(Vh + rr * 240 + col - 240) = v;
                }
            }
        }
    }
}

// =======================================================================
// All-scale score GEMM, ldmatrix, 3-stage cp.async pipeline, fused stats.
// z = (bh<<2)|sc (clusters same-bh blocks for L2 reuse of KhT).
// =======================================================================
__global__ __launch_bounds__(256)
void score_all(const float* __restrict__ Qh, const float* __restrict__ KhT,
               float* __restrict__ S, float* __restrict__ part, float alpha)
{
    const int z = blockIdx.z, sc = z & 3, bh = z >> 2;
    const int d = 16 << sc;
    const int m0 = blockIdx.y * 64;
    if (m0 >= d) return;

    const float* A = Qh  + 65536L * (d - 16) + (long)bh * d * 1024;  // [d][1024]
    const float* B = KhT + (long)bh * 240 * 1024;                    // [240][1024]
    float*       C = S   + 15360L * (d - 16) + (long)bh * d * 240;   // [d][240]

    const int tid = threadIdx.x, lane = tid & 31, warp = tid >> 5;
    const int wm = warp >> 2, wn = warp & 3;      // 2 x 4 warps, warp tile 32 x 64
    const int g = lane >> 2, c4 = lane & 3;

    __shared__ float sA[3][64 * 20];
    __shared__ float sB[3][256 * 20];
    __shared__ float red[16];

    float acc[2][8][4] = {};

    const int lr = tid >> 2, lq = (tid & 3) * 4;

    auto fill = [&](int s, int k0) {
        cpasync16((uint32_t)__cvta_generic_to_shared(&sA[s][lr * 20 + lq]),
                  A + (long)(m0 + lr) * 1024 + k0 + lq, (m0 + lr < d) ? 16 : 0);
        #pragma unroll
        for (int rd = 0; rd < 4; rd++) {
            int row = lr + rd * 64;
            cpasync16((uint32_t)__cvta_generic_to_shared(&sB[s][row * 20 + lq]),
                      B + (long)row * 1024 + k0 + lq, (row < 240) ? 16 : 0);
        }
    };

    const uint32_t sAb = (uint32_t)__cvta_generic_to_shared(sA);
    const uint32_t sBb = (uint32_t)__cvta_generic_to_shared(sB);
    const int a_row = wm * 32 + (lane & 15);
    const int a_kh  = (lane >> 4) * 4;
    const int b_row = wn * 64 + ((lane & 16) >> 1) + (lane & 7);
    const int b_kh  = ((lane >> 3) & 1) * 4;

    const int KT = 64;   // K = 1024, BK = 16
    fill(0, 0);
    asm volatile("cp.async.commit_group;\n");
    fill(1, 16);
    asm volatile("cp.async.commit_group;\n");

    int cur = 0, pf = 2;   // compute stage, prefetch stage
    for (int kt = 0; kt < KT; kt++) {
        if (kt + 2 < KT) fill(pf, (kt + 2) << 4);
        asm volatile("cp.async.commit_group;\n");
        asm volatile("cp.async.wait_group 2;\n");
        __syncthreads();
        const uint32_t aBase = sAb + (uint32_t)(cur * 64 * 20) * 4u;
        const uint32_t bBase = sBb + (uint32_t)(cur * 256 * 20) * 4u;
        #pragma unroll
        for (int ks = 0; ks < 16; ks += 8) {
            uint32_t af[2][4], bfr[16];
            #pragma unroll
            for (int fm = 0; fm < 2; fm++)
                ldsm4(af[fm], aBase + (uint32_t)((a_row + fm * 16) * 20 + ks + a_kh) * 4u);
            #pragma unroll
            for (int fp = 0; fp < 4; fp++)
                ldsm4(&bfr[fp * 4], bBase + (uint32_t)((b_row + fp * 16) * 20 + ks + b_kh) * 4u);
            #pragma unroll
            for (int fm = 0; fm < 2; fm++)
                #pragma unroll
                for (int fn = 0; fn < 8; fn++)
                    mma_tf32(acc[fm][fn], af[fm], &bfr[(fn >> 1) * 4 + (fn & 1) * 2]);
        }
        __syncthreads();
        if (++cur == 3) cur = 0;
        if (++pf == 3) pf = 0;
    }

    float ls = 0.f, lss = 0.f;
    #pragma unroll
    for (int fm = 0; fm < 2; fm++) {
        int row0 = m0 + wm * 32 + fm * 16 + g;
        #pragma unroll
        for (int half = 0; half < 2; half++) {
            int r = row0 + half * 8;
            if (r >= d) continue;
            #pragma unroll
            for (int fn = 0; fn < 8; fn++) {
                int col = wn * 64 + fn * 8 + c4 * 2;
                if (col >= 240) continue;
                float v0 = alpha * acc[fm][fn][half * 2];
                float v1 = alpha * acc[fm][fn][half * 2 + 1];
                *(float2*)(C + (long)r * 240 + col) = make_float2(v0, v1);
                ls  += v0 + v1;
                lss += v0 * v0 + v1 * v1;
            }
        }
    }

    #pragma unroll
    for (int o = 16; o; o >>= 1) {
        ls  += __shfl_xor_sync(0xffffffffu, ls,  o);
        lss += __shfl_xor_sync(0xffffffffu, lss, o);
    }
    if (lane == 0) { red[warp] = ls; red[8 + warp] = lss; }
    __syncthreads();
    if (tid == 0) {
        float s = 0.f, ss = 0.f;
        #pragma unroll
        for (int j = 0; j < 8; j++) { s += red[j]; ss += red[8 + j]; }
        int idx = ((sc << 6) | bh) * 2 + blockIdx.y;
        part[2 * idx]     = s;
        part[2 * idx + 1] = ss;
    }
}

// =======================================================================
// Softmax apply (inline stats from partials): one warp per score row.
// =======================================================================
__global__ __launch_bounds__(256)
void softmax_all(float* __restrict__ S, const float* __restrict__ part)
{
    int row = blockIdx.x * 8 + (threadIdx.x >> 5);
    int l = threadIdx.x & 31;
    int sc, loc;
    if (row < 1024)      { sc = 0; loc = row; }
    else if (row < 3072) { sc = 1; loc = row - 1024; }
    else if (row < 7168) { sc = 2; loc = row - 3072; }
    else                 { sc = 3; loc = row - 7168; }
    int d = 16 << sc, dc = d - 16;
    int bh = loc >> (4 + sc);
    float* p = S + 15360L * dc + (long)loc * 240;

    int idx = (sc << 6) | bh;
    int nb = (d > 64) ? 2 : 1;
    float s = 0.f, ss = 0.f;
    for (int j = 0; j < nb; j++) {
        s  += part[2 * (idx * 2 + j)];
        ss += part[2 * (idx * 2 + j) + 1];
    }
    float count = (float)(d * 240);
    float mean = s / count;
    float var  = ss / count - mean * mean;
    float istd = rsqrtf(var + 1e-5f);

    float v[8];
    float mx = -1e30f;
    #pragma unroll
    for (int t = 0; t < 8; t++) {
        int k = l + t * 32;
        float x = (k < 240) ? (p[k] - mean) * istd : -1e30f;
        v[t] = x; mx = fmaxf(mx, x);
    }
    #pragma unroll
    for (int o = 16; o; o >>= 1) mx = fmaxf(mx, __shfl_xor_sync(0xffffffffu, mx, o));
    float se = 0.f;
    #pragma unroll
    for (int t = 0; t < 8; t++) {
        int k = l + t * 32;
        float e = (k < 240) ? __expf(v[t] - mx) : 0.f;
        v[t] = e; se += e;
    }
    #pragma unroll
    for (int o = 16; o; o >>= 1) se += __shfl_xor_sync(0xffffffffu, se, o);
    float inv = 1.f / se;
    #pragma unroll
    for (int t = 0; t < 8; t++) {
        int k = l + t * 32;
        if (k < 240) p[k] = rndtf(v[t] * inv);
    }
}

extern "C" void kernel_launch(void* const* d_in, const int* in_sizes, int n_in,
                              void* d_out, int out_size)
{
    const float* emb[4]  = { (const float*)d_in[0], (const float*)d_in[1],
                             (const float*)d_in[2], (const float*)d_in[3] };
    const float* emb_all = (const float*)d_in[4];
    const float* Wq[4]   = { (const float*)d_in[5], (const float*)d_in[6],
                             (const float*)d_in[7], (const float*)d_in[8] };
    const float* Wk      = (const float*)d_in[9];
    const float* Wv      = (const float*)d_in[10];
    const float* Wo[4]   = { (const float*)d_in[11], (const float*)d_in[12],
                             (const float*)d_in[13], (const float*)d_in[14] };
    float* out = (float*)d_out;

    float *pKhT, *pVh, *pQh, *pS, *pCtxT, *pPart;
    cudaGetSymbolAddress((void**)&pKhT,  g_KhT);
    cudaGetSymbolAddress((void**)&pVh,   g_Vh);
    cudaGetSymbolAddress((void**)&pQh,   g_Qh);
    cudaGetSymbolAddress((void**)&pS,    g_S);
    cudaGetSymbolAddress((void**)&pCtxT, g_ctxT);
    cudaGetSymbolAddress((void**)&pPart, g_part);

    const int chArr[4] = {64, 128, 256, 512};
    const int chcum[4] = {0, 64, 192, 448};

    // 1) fused gather + K/V projection (Kh transposed)
    kvproj<<<dim3(4, 512), 256>>>(emb_all, Wk, Wv, pKhT, pVh);

    // 2) all Q projections, one launch
    qproj_all<<<dim3(16, 2, 256), 128>>>(emb[0], emb[1], emb[2], emb[3],
                                         Wq[0], Wq[1], Wq[2], Wq[3], pQh);

    const float alpha = 1.f / sqrtf((float)KVc);

    // 3) all score GEMMs, one launch (ldmatrix, 3-stage pipeline, fused stats)
    score_all<<<dim3(1, 2, 256), 256>>>(pQh, pKhT, pS, pPart, alpha);

    // 4) softmax (stats computed inline from partials)
    softmax_all<<<15360 / 8, 256>>>(pS, pPart);

    // 5) all ctx GEMMs, one launch (strided store into ctxT [B,N,CH])
    ctx_all<<<dim3(16, 2, 256), 128>>>(pS, pVh, pCtxT);

    // 6) output projections
    for (int sc = 0; sc < 4; sc++) {
        int CH = chArr[sc];
        float* ctxT = pCtxT + (long)Bc * Nc * chcum[sc];
        float* Osc  = out   + (long)Bc * Nc * chcum[sc];
        if (CH >= 256) {
            dim3 grid(CH / 128, (Bc * Nc) / 128);
            gemm128<false, true><<<grid, 256>>>(ctxT, Wo[sc], Osc,
                                                Bc * Nc, CH, CH, CH, CH, CH, 1.f);
        } else {
            dim3 grid(CH / 64, (Bc * Nc) / 64, 1);
            gemm64<false, false, true, false><<<grid, 128>>>(ctxT, Wo[sc], Osc,
                Bc * Nc, CH, CH, CH, CH, CH, 1, 1,
                0, 0, 0, 0, 0, 0, 1.f);
        }
    }
}

// round 13
// speedup vs baseline: 1.1362x; 1.1214x over previous
#include <cuda_runtime.h>
#include <math.h>
#include <stdint.h>

// Problem constants
#define Bc 16
#define Nc 1024
#define Hc 4
#define KVc 960
#define Dc 240            // KV/4, per-head K/V feature dim

#define SZ_BHND (Bc*Hc*Nc*Dc)   // 15,728,640

// ---------------- scratch (static device globals; no allocation) ----------
__device__ float g_KhT [SZ_BHND];           // [bh][240][1024]  (tf32-rounded, TRANSPOSED)
__device__ float g_Vh  [SZ_BHND];           // [bh][1024][240]  (tf32-rounded)
__device__ float g_Qh  [SZ_BHND];           // [bh][240][1024]: rows stacked by scale (tf32-rounded)
__device__ float g_S   [Bc*Hc*Dc*Dc];       // per-scale [bh][d][240]
__device__ float g_ctxT[Bc*Nc*KVc];         // per-scale [B,N,CH]   (tf32-rounded)
__device__ float g_part[2048];              // [bh][y][sc][2] score partials (sum, sumsq)

// ---------------- helpers ----------------
__device__ __forceinline__ void cpasync16(uint32_t dst, const void* src, int sz) {
    asm volatile("cp.async.ca.shared.global [%0], [%1], 16, %2;\n"
                 :: "r"(dst), "l"(src), "r"(sz));
}
__device__ __forceinline__ uint32_t f2tf(float f) {
    uint32_t r; asm("cvt.rna.tf32.f32 %0, %1;" : "=r"(r) : "f"(f)); return r;
}
__device__ __forceinline__ float rndtf(float f) { return __uint_as_float(f2tf(f)); }

template<bool CVT>
__device__ __forceinline__ uint32_t ldop(float v) {
    return CVT ? f2tf(v) : __float_as_uint(v);
}
__device__ __forceinline__ void mma_tf32(float* acc, const uint32_t* a, const uint32_t* b) {
    asm volatile("mma.sync.aligned.m16n8k8.row.col.f32.tf32.tf32.f32 "
                 "{%0,%1,%2,%3}, {%4,%5,%6,%7}, {%8,%9}, {%0,%1,%2,%3};\n"
                 : "+f"(acc[0]), "+f"(acc[1]), "+f"(acc[2]), "+f"(acc[3])
                 : "r"(a[0]), "r"(a[1]), "r"(a[2]), "r"(a[3]), "r"(b[0]), "r"(b[1]));
}
__device__ __forceinline__ void ldsm4(uint32_t* r, uint32_t addr) {
    asm volatile("ldmatrix.sync.aligned.m8n8.x4.shared.b16 {%0,%1,%2,%3}, [%4];\n"
                 : "=r"(r[0]), "=r"(r[1]), "=r"(r[2]), "=r"(r[3]) : "r"(addr));
}

// =======================================================================
// Shared 64x64 GEMM body: 128 threads, BK=16, NT (B [Nn][K] K-contig).
// =======================================================================
template<bool SC, bool CVTA, bool CVTB, bool RND>
__device__ __forceinline__
void gemm64_body(const float* __restrict__ A, const float* __restrict__ B, float* __restrict__ C,
                 int M, int Nn, int K, int lda, int ldb, int ldc, int ldcC,
                 int m0, int n0, float alpha)
{
    const int tid = threadIdx.x, lane = tid & 31, warp = tid >> 5;
    const int wm = warp >> 1, wn = warp & 1;
    const int g = lane >> 2, c4 = lane & 3;

    __shared__ float sA[2][64 * 20];
    __shared__ float sB[2][64 * 20];

    float acc[2][4][4] = {};

    const int ar = tid >> 1, ac = (tid & 1) * 8;

    auto fill = [&](int s, int k0) {
        const float* ap = A + (long)(m0 + ar) * lda + k0 + ac;
        int sa = (m0 + ar < M) ? 16 : 0;
        cpasync16((uint32_t)__cvta_generic_to_shared(&sA[s][ar * 20 + ac]),     ap,     sa);
        cpasync16((uint32_t)__cvta_generic_to_shared(&sA[s][ar * 20 + ac + 4]), ap + 4, sa);
        const float* bp = B + (long)(n0 + ar) * ldb + k0 + ac;
        int sb = (n0 + ar < Nn) ? 16 : 0;
        cpasync16((uint32_t)__cvta_generic_to_shared(&sB[s][ar * 20 + ac]),     bp,     sb);
        cpasync16((uint32_t)__cvta_generic_to_shared(&sB[s][ar * 20 + ac + 4]), bp + 4, sb);
    };

    const int KT = K >> 4;
    fill(0, 0);
    asm volatile("cp.async.commit_group;\n");
    for (int kt = 0; kt < KT; kt++) {
        int cur = kt & 1;
        if (kt + 1 < KT) fill(cur ^ 1, (kt + 1) << 4);
        asm volatile("cp.async.commit_group;\n");
        asm volatile("cp.async.wait_group 1;\n");
        __syncthreads();
        const float* a_s = sA[cur];
        const float* b_s = sB[cur];
        #pragma unroll
        for (int ks = 0; ks < 16; ks += 8) {
            uint32_t af[2][4], bf[4][2];
            #pragma unroll
            for (int fm = 0; fm < 2; fm++) {
                int mb = wm * 32 + fm * 16;
                af[fm][0] = ldop<CVTA>(a_s[(mb + g    ) * 20 + ks + c4]);
                af[fm][1] = ldop<CVTA>(a_s[(mb + g + 8) * 20 + ks + c4]);
                af[fm][2] = ldop<CVTA>(a_s[(mb + g    ) * 20 + ks + c4 + 4]);
                af[fm][3] = ldop<CVTA>(a_s[(mb + g + 8) * 20 + ks + c4 + 4]);
            }
            #pragma unroll
            for (int fn = 0; fn < 4; fn++) {
                int nb = wn * 32 + fn * 8 + g;
                bf[fn][0] = ldop<CVTB>(b_s[nb * 20 + ks + c4]);
                bf[fn][1] = ldop<CVTB>(b_s[nb * 20 + ks + c4 + 4]);
            }
            #pragma unroll
            for (int fm = 0; fm < 2; fm++)
                #pragma unroll
                for (int fn = 0; fn < 4; fn++)
                    mma_tf32(acc[fm][fn], af[fm], bf[fn]);
        }
        __syncthreads();
    }

    #pragma unroll
    for (int fm = 0; fm < 2; fm++) {
        int row0 = m0 + wm * 32 + fm * 16 + g;
        #pragma unroll
        for (int half = 0; half < 2; half++) {
            int r = row0 + half * 8;
            if (r >= M) continue;
            #pragma unroll
            for (int fn = 0; fn < 4; fn++) {
                int col = n0 + wn * 32 + fn * 8 + c4 * 2;
                if (col >= Nn) continue;
                float v0 = alpha * acc[fm][fn][half * 2 + 0];
                float v1 = alpha * acc[fm][fn][half * 2 + 1];
                if (RND) { v0 = rndtf(v0); v1 = rndtf(v1); }
                if (SC) {
                    C[(long)r * ldc + (long)col * ldcC] = v0;
                    C[(long)r * ldc + (long)(col + 1) * ldcC] = v1;
                } else {
                    *(float2*)(C + (long)r * ldc + col) = make_float2(v0, v1);
                }
            }
        }
    }
}

// Generic 64x64 kernel (used for out-proj CH=64/128)
template<bool SC, bool CVTA, bool CVTB, bool RND>
__global__ __launch_bounds__(128)
void gemm64(const float* __restrict__ A, const float* __restrict__ B, float* __restrict__ C,
            int M, int Nn, int K, int lda, int ldb, int ldc, int ldcC, int Hs,
            long aB, long aH, long bB, long bH, long cB, long cH, float alpha)
{
    int z = blockIdx.z, zb = z / Hs, zh = z - zb * Hs;
    gemm64_body<SC, CVTA, CVTB, RND>(A + zb * aB + zh * aH, B + zb * bB + zh * bH,
                                     C + zb * cB + zh * cH,
                                     M, Nn, K, lda, ldb, ldc, ldcC,
                                     blockIdx.y * 64, blockIdx.x * 64, alpha);
}

// All-scale Q projection: z = (sc<<6)|bh.
// Output STACKED: QhAll[bh][240][1024], rows offset by dcum = d-16. Rounded.
__global__ __launch_bounds__(128)
void qproj_all(const float* __restrict__ e1, const float* __restrict__ e2,
               const float* __restrict__ e3, const float* __restrict__ e4,
               const float* __restrict__ w1, const float* __restrict__ w2,
               const float* __restrict__ w3, const float* __restrict__ w4,
               float* __restrict__ Qh)
{
    const int z = blockIdx.z, sc = z >> 6, bh = z & 63, b = bh >> 2, h = bh & 3;
    const int d = 16 << sc, CH = d * 4;
    const int m0 = blockIdx.y * 64;
    if (m0 >= d) return;
    const float* emb = sc == 0 ? e1 : sc == 1 ? e2 : sc == 2 ? e3 : e4;
    const float* Wq  = sc == 0 ? w1 : sc == 1 ? w2 : sc == 2 ? w3 : w4;
    const float* A = Wq + (long)h * d * d;                 // [d][d]
    const float* B = emb + (long)b * 1024 * CH + h * d;    // [1024][CH]
    float*       C = Qh + (long)bh * 240 * 1024 + (long)(d - 16) * 1024;
    gemm64_body<false, true, true, true>(A, B, C, d, 1024, d, d, CH, 1024, 1,
                                         m0, blockIdx.x * 64, 1.f);
}

// All-scale ctx GEMM: z = (sc<<6)|bh. ctxT[b][n][dd*H+h], rounded.
__global__ __launch_bounds__(128)
void ctx_all(const float* __restrict__ S, const float* __restrict__ Vh,
             float* __restrict__ ctxT)
{
    const int z = blockIdx.z, sc = z >> 6, bh = z & 63, b = bh >> 2, h = bh & 3;
    const int d = 16 << sc, CH = d * 4;
    const int m0 = blockIdx.y * 64;
    if (m0 >= d) return;
    const float* A = S  + 15360L * (d - 16) + (long)bh * d * 240;   // [d][240]
    const float* B = Vh + (long)bh * 1024 * 240;                    // [1024][240]
    float*       C = ctxT + 65536L * (d - 16) + (long)b * 1024 * CH + h;
    gemm64_body<true, false, false, true>(A, B, C, d, 1024, 240, 240, 240, Hc, CH,
                                          m0, blockIdx.x * 64, 1.f);
}

// =======================================================================
// 128x128 tile, 256 threads, BK=16 — NT: C = alpha*A*B^T
// =======================================================================
template<bool CVTA, bool CVTB>
__global__ __launch_bounds__(256)
void gemm128(const float* __restrict__ A, const float* __restrict__ B, float* __restrict__ C,
             int M, int Nn, int K, int lda, int ldb, int ldc, float alpha)
{
    const int m0 = blockIdx.y * 128, n0 = blockIdx.x * 128;
    const int tid = threadIdx.x, lane = tid & 31, warp = tid >> 5;
    const int wm = warp >> 1, wn = warp & 1;   // 4x2 warps: warp tile 32x64
    const int g = lane >> 2, c4 = lane & 3;

    __shared__ float sA[2][128 * 20];
    __shared__ float sB[2][128 * 20];

    float acc[2][8][4] = {};

    const int ar = tid >> 1, ac = (tid & 1) * 8;

    auto fill = [&](int s, int k0) {
        const float* ap = A + (long)(m0 + ar) * lda + k0 + ac;
        int sa = (m0 + ar < M) ? 16 : 0;
        cpasync16((uint32_t)__cvta_generic_to_shared(&sA[s][ar * 20 + ac]),     ap,     sa);
        cpasync16((uint32_t)__cvta_generic_to_shared(&sA[s][ar * 20 + ac + 4]), ap + 4, sa);
        const float* bp = B + (long)(n0 + ar) * ldb + k0 + ac;
        int sb = (n0 + ar < Nn) ? 16 : 0;
        cpasync16((uint32_t)__cvta_generic_to_shared(&sB[s][ar * 20 + ac]),     bp,     sb);
        cpasync16((uint32_t)__cvta_generic_to_shared(&sB[s][ar * 20 + ac + 4]), bp + 4, sb);
    };

    const int KT = K >> 4;
    fill(0, 0);
    asm volatile("cp.async.commit_group;\n");
    for (int kt = 0; kt < KT; kt++) {
        int cur = kt & 1;
        if (kt + 1 < KT) fill(cur ^ 1, (kt + 1) << 4);
        asm volatile("cp.async.commit_group;\n");
        asm volatile("cp.async.wait_group 1;\n");
        __syncthreads();
        const float* a_s = sA[cur];
        const float* b_s = sB[cur];
        #pragma unroll
        for (int ks = 0; ks < 16; ks += 8) {
            uint32_t af[2][4], bf[8][2];
            #pragma unroll
            for (int fm = 0; fm < 2; fm++) {
                int mb = wm * 32 + fm * 16;
                af[fm][0] = ldop<CVTA>(a_s[(mb + g    ) * 20 + ks + c4]);
                af[fm][1] = ldop<CVTA>(a_s[(mb + g + 8) * 20 + ks + c4]);
                af[fm][2] = ldop<CVTA>(a_s[(mb + g    ) * 20 + ks + c4 + 4]);
                af[fm][3] = ldop<CVTA>(a_s[(mb + g + 8) * 20 + ks + c4 + 4]);
            }
            #pragma unroll
            for (int fn = 0; fn < 8; fn++) {
                int nb = wn * 64 + fn * 8 + g;
                bf[fn][0] = ldop<CVTB>(b_s[nb * 20 + ks + c4]);
                bf[fn][1] = ldop<CVTB>(b_s[nb * 20 + ks + c4 + 4]);
            }
            #pragma unroll
            for (int fm = 0; fm < 2; fm++)
                #pragma unroll
                for (int fn = 0; fn < 8; fn++)
                    mma_tf32(acc[fm][fn], af[fm], bf[fn]);
        }
        __syncthreads();
    }

    #pragma unroll
    for (int fm = 0; fm < 2; fm++) {
        int row0 = m0 + wm * 32 + fm * 16 + g;
        #pragma unroll
        for (int half = 0; half < 2; half++) {
            int r = row0 + half * 8;
            if (r >= M) continue;
            #pragma unroll
            for (int fn = 0; fn < 8; fn++) {
                int col = n0 + wn * 64 + fn * 8 + c4 * 2;
                if (col >= Nn) continue;
                *(float2*)(C + (long)r * ldc + col) =
                    make_float2(alpha * acc[fm][fn][half * 2], alpha * acc[fm][fn][half * 2 + 1]);
            }
        }
    }
}

// =======================================================================
// Fused gather + K/V projection (128x128 tile). Rounded outputs.
// Kh written TRANSPOSED: KhT[bh][c][n]; Vh written [bh][n][c].
// =======================================================================
__global__ __launch_bounds__(256)
void kvproj(const float* __restrict__ emb_all, const float* __restrict__ Wk,
            const float* __restrict__ Wv, float* __restrict__ KhT, float* __restrict__ Vh)
{
    const int m0 = blockIdx.y * 128, n0 = blockIdx.x * 128;
    const int tid = threadIdx.x, lane = tid & 31, warp = tid >> 5;
    const int wm = warp >> 1, wn = warp & 1;
    const int g = lane >> 2, c4 = lane & 3;

    __shared__ float sA[2][128 * 20];
    __shared__ float sB[2][128 * 20];

    float acc[2][8][4] = {};

    const int ar = tid >> 1, ac = (tid & 1) * 8;

    int m = m0 + ar;
    int b = m >> 12, h = (m >> 10) & 3, n = m & 1023;
    const float* abase = emb_all + ((long)(b * Nc + n)) * KVc;

    int r = n0 + ar;
    const float* bbase;
    int bsz;
    if (r < 240)      { bbase = Wk + (long)r * 240;         bsz = 16; }
    else if (r < 480) { bbase = Wv + (long)(r - 240) * 240; bsz = 16; }
    else              { bbase = Wk;                          bsz = 0; }

    auto seg = [&](int j) {
        return j < 16 ? 16 * h + j
             : j < 48 ? 64 + 32 * h + (j - 16)
             : j < 112 ? 192 + 64 * h + (j - 48)
             : 448 + 128 * h + (j - 112);
    };

    auto fill = [&](int s, int k0) {
        cpasync16((uint32_t)__cvta_generic_to_shared(&sA[s][ar * 20 + ac]),     abase + seg(k0 + ac),     16);
        cpasync16((uint32_t)__cvta_generic_to_shared(&sA[s][ar * 20 + ac + 4]), abase + seg(k0 + ac + 4), 16);
        cpasync16((uint32_t)__cvta_generic_to_shared(&sB[s][ar * 20 + ac]),     bbase + k0 + ac,          bsz);
        cpasync16((uint32_t)__cvta_generic_to_shared(&sB[s][ar * 20 + ac + 4]), bbase + k0 + ac + 4,      bsz);
    };

    const int KT = Dc >> 4;   // 15
    fill(0, 0);
    asm volatile("cp.async.commit_group;\n");
    for (int kt = 0; kt < KT; kt++) {
        int cur = kt & 1;
        if (kt + 1 < KT) fill(cur ^ 1, (kt + 1) << 4);
        asm volatile("cp.async.commit_group;\n");
        asm volatile("cp.async.wait_group 1;\n");
        __syncthreads();
        const float* a_s = sA[cur];
        const float* b_s = sB[cur];
        #pragma unroll
        for (int ks = 0; ks < 16; ks += 8) {
            uint32_t af[2][4], bf[8][2];
            #pragma unroll
            for (int fm = 0; fm < 2; fm++) {
                int mb = wm * 32 + fm * 16;
                af[fm][0] = f2tf(a_s[(mb + g    ) * 20 + ks + c4]);
                af[fm][1] = f2tf(a_s[(mb + g + 8) * 20 + ks + c4]);
                af[fm][2] = f2tf(a_s[(mb + g    ) * 20 + ks + c4 + 4]);
                af[fm][3] = f2tf(a_s[(mb + g + 8) * 20 + ks + c4 + 4]);
            }
            #pragma unroll
            for (int fn = 0; fn < 8; fn++) {
                int nb = wn * 64 + fn * 8 + g;
                bf[fn][0] = f2tf(b_s[nb * 20 + ks + c4]);
                bf[fn][1] = f2tf(b_s[nb * 20 + ks + c4 + 4]);
            }
            #pragma unroll
            for (int fm = 0; fm < 2; fm++)
                #pragma unroll
                for (int fn = 0; fn < 8; fn++)
                    mma_tf32(acc[fm][fn], af[fm], bf[fn]);
        }
        __syncthreads();
    }

    #pragma unroll
    for (int fm = 0; fm < 2; fm++) {
        int row0 = wm * 32 + fm * 16 + g;
        #pragma unroll
        for (int half = 0; half < 2; half++) {
            long rr = (long)(m0 + row0 + half * 8);
            int bh_o = (int)(rr >> 10), n_o = (int)(rr & 1023);
            #pragma unroll
            for (int fn = 0; fn < 8; fn++) {
                int col = n0 + wn * 64 + fn * 8 + c4 * 2;
                float2 v = make_float2(rndtf(acc[fm][fn][half * 2]),
                                       rndtf(acc[fm][fn][half * 2 + 1]));
                if (col < 240) {
                    float* p = KhT + ((long)bh_o * 240 + col) * 1024 + n_o;
                    p[0] = v.x; p[1024] = v.y;
                } else if (col < 480) {
                    *(float2*)(Vh + rr * 240 + col - 240) = v;
                }
            }
        }
    }
}

// =======================================================================
// Stacked score GEMM: one block row-tile of the [240,1024]x[1024,240] GEMM
// per (bh, y). All scales of one bh share the same KhT (read once).
// grid (1, 4, 64). Rows map back to per-scale S regions; per-scale stats.
// =======================================================================
__global__ __launch_bounds__(256)
void score_all(const float* __restrict__ Qh, const float* __restrict__ KhT,
               float* __restrict__ S, float* __restrict__ part, float alpha)
{
    const int bh = blockIdx.z;
    const int m0 = blockIdx.y * 64;          // rows m0..m0+63 of the stacked 240

    const float* A = Qh  + (long)bh * 240 * 1024;   // [240][1024] stacked
    const float* B = KhT + (long)bh * 240 * 1024;   // [240][1024]

    const int tid = threadIdx.x, lane = tid & 31, warp = tid >> 5;
    const int wm = warp >> 2, wn = warp & 3;      // 2 x 4 warps, warp tile 32 x 64
    const int g = lane >> 2, c4 = lane & 3;

    __shared__ float sA[2][64 * 20];
    __shared__ float sB[2][256 * 20];
    __shared__ float red[64];

    float acc[2][8][4] = {};

    const int lr = tid >> 2, lq = (tid & 3) * 4;

    auto fill = [&](int s, int k0) {
        cpasync16((uint32_t)__cvta_generic_to_shared(&sA[s][lr * 20 + lq]),
                  A + (long)(m0 + lr) * 1024 + k0 + lq, (m0 + lr < 240) ? 16 : 0);
        #pragma unroll
        for (int rd = 0; rd < 4; rd++) {
            int row = lr + rd * 64;
            cpasync16((uint32_t)__cvta_generic_to_shared(&sB[s][row * 20 + lq]),
                      B + (long)row * 1024 + k0 + lq, (row < 240) ? 16 : 0);
        }
    };

    const uint32_t sAb = (uint32_t)__cvta_generic_to_shared(sA);
    const uint32_t sBb = (uint32_t)__cvta_generic_to_shared(sB);
    const int a_row = wm * 32 + (lane & 15);
    const int a_kh  = (lane >> 4) * 4;
    const int b_row = wn * 64 + ((lane & 16) >> 1) + (lane & 7);
    const int b_kh  = ((lane >> 3) & 1) * 4;

    const int KT = 64;   // K = 1024, BK = 16
    fill(0, 0);
    asm volatile("cp.async.commit_group;\n");
    for (int kt = 0; kt < KT; kt++) {
        int cur = kt & 1;
        if (kt + 1 < KT) fill(cur ^ 1, (kt + 1) << 4);
        asm volatile("cp.async.commit_group;\n");
        asm volatile("cp.async.wait_group 1;\n");
        __syncthreads();
        const uint32_t aBase = sAb + (uint32_t)(cur * 64 * 20) * 4u;
        const uint32_t bBase = sBb + (uint32_t)(cur * 256 * 20) * 4u;
        #pragma unroll
        for (int ks = 0; ks < 16; ks += 8) {
            uint32_t af[2][4], bfr[16];
            #pragma unroll
            for (int fm = 0; fm < 2; fm++)
                ldsm4(af[fm], aBase + (uint32_t)((a_row + fm * 16) * 20 + ks + a_kh) * 4u);
            #pragma unroll
            for (int fp = 0; fp < 4; fp++)
                ldsm4(&bfr[fp * 4], bBase + (uint32_t)((b_row + fp * 16) * 20 + ks + b_kh) * 4u);
            #pragma unroll
            for (int fm = 0; fm < 2; fm++)
                #pragma unroll
                for (int fn = 0; fn < 8; fn++)
                    mma_tf32(acc[fm][fn], af[fm], &bfr[(fn >> 1) * 4 + (fn & 1) * 2]);
        }
        __syncthreads();
    }

    // epilogue: route rows to per-scale S regions; per-scale stats buckets
    float ls[4] = {}, lss[4] = {};
    #pragma unroll
    for (int fm = 0; fm < 2; fm++) {
        int row0 = m0 + wm * 32 + fm * 16 + g;
        #pragma unroll
        for (int half = 0; half < 2; half++) {
            int r = row0 + half * 8;
            if (r >= 240) continue;
            int sc_r = (r < 16) ? 0 : (r < 48) ? 1 : (r < 112) ? 2 : 3;
            int d_r = 16 << sc_r, dcum = d_r - 16;
            float* Crow = S + 15360L * dcum + ((long)bh * d_r + (r - dcum)) * 240;
            float rs = 0.f, rss = 0.f;
            #pragma unroll
            for (int fn = 0; fn < 8; fn++) {
                int col = wn * 64 + fn * 8 + c4 * 2;
                if (col >= 240) continue;
                float v0 = alpha * acc[fm][fn][half * 2];
                float v1 = alpha * acc[fm][fn][half * 2 + 1];
                *(float2*)(Crow + col) = make_float2(v0, v1);
                rs  += v0 + v1;
                rss += v0 * v0 + v1 * v1;
            }
            #pragma unroll
            for (int s = 0; s < 4; s++) {
                ls[s]  += (sc_r == s) ? rs  : 0.f;
                lss[s] += (sc_r == s) ? rss : 0.f;
            }
        }
    }

    #pragma unroll
    for (int s = 0; s < 4; s++) {
        #pragma unroll
        for (int o = 16; o; o >>= 1) {
            ls[s]  += __shfl_xor_sync(0xffffffffu, ls[s],  o);
            lss[s] += __shfl_xor_sync(0xffffffffu, lss[s], o);
        }
    }
    if (lane == 0) {
        #pragma unroll
        for (int s = 0; s < 4; s++) {
            red[warp * 8 + s]     = ls[s];
            red[warp * 8 + 4 + s] = lss[s];
        }
    }
    __syncthreads();
    if (tid < 4) {
        float s = 0.f, ss = 0.f;
        #pragma unroll
        for (int j = 0; j < 8; j++) {
            s  += red[j * 8 + tid];
            ss += red[j * 8 + 4 + tid];
        }
        int idx = ((bh * 4 + blockIdx.y) * 4 + tid) * 2;
        part[idx]     = s;
        part[idx + 1] = ss;
    }
}

// =======================================================================
// Softmax apply (inline stats from partials): one warp per score row.
// =======================================================================
__global__ __launch_bounds__(256)
void softmax_all(float* __restrict__ S, const float* __restrict__ part)
{
    int row = blockIdx.x * 8 + (threadIdx.x >> 5);
    int l = threadIdx.x & 31;
    int sc, loc;
    if (row < 1024)      { sc = 0; loc = row; }
    else if (row < 3072) { sc = 1; loc = row - 1024; }
    else if (row < 7168) { sc = 2; loc = row - 3072; }
    else                 { sc = 3; loc = row - 7168; }
    int d = 16 << sc, dc = d - 16;
    int bh = loc >> (4 + sc);
    float* p = S + 15360L * dc + (long)loc * 240;

    float s = 0.f, ss = 0.f;
    #pragma unroll
    for (int by = 0; by < 4; by++) {
        int idx = ((bh * 4 + by) * 4 + sc) * 2;
        s  += part[idx];
        ss += part[idx + 1];
    }
    float count = (float)(d * 240);
    float mean = s / count;
    float var  = ss / count - mean * mean;
    float istd = rsqrtf(var + 1e-5f);

    float v[8];
    float mx = -1e30f;
    #pragma unroll
    for (int t = 0; t < 8; t++) {
        int k = l + t * 32;
        float x = (k < 240) ? (p[k] - mean) * istd : -1e30f;
        v[t] = x; mx = fmaxf(mx, x);
    }
    #pragma unroll
    for (int o = 16; o; o >>= 1) mx = fmaxf(mx, __shfl_xor_sync(0xffffffffu, mx, o));
    float se = 0.f;
    #pragma unroll
    for (int t = 0; t < 8; t++) {
        int k = l + t * 32;
        float e = (k < 240) ? __expf(v[t] - mx) : 0.f;
        v[t] = e; se += e;
    }
    #pragma unroll
    for (int o = 16; o; o >>= 1) se += __shfl_xor_sync(0xffffffffu, se, o);
    float inv = 1.f / se;
    #pragma unroll
    for (int t = 0; t < 8; t++) {
        int k = l + t * 32;
        if (k < 240) p[k] = rndtf(v[t] * inv);
    }
}

extern "C" void kernel_launch(void* const* d_in, const int* in_sizes, int n_in,
                              void* d_out, int out_size)
{
    const float* emb[4]  = { (const float*)d_in[0], (const float*)d_in[1],
                             (const float*)d_in[2], (const float*)d_in[3] };
    const float* emb_all = (const float*)d_in[4];
    const float* Wq[4]   = { (const float*)d_in[5], (const float*)d_in[6],
                             (const float*)d_in[7], (const float*)d_in[8] };
    const float* Wk      = (const float*)d_in[9];
    const float* Wv      = (const float*)d_in[10];
    const float* Wo[4]   = { (const float*)d_in[11], (const float*)d_in[12],
                             (const float*)d_in[13], (const float*)d_in[14] };
    float* out = (float*)d_out;

    float *pKhT, *pVh, *pQh, *pS, *pCtxT, *pPart;
    cudaGetSymbolAddress((void**)&pKhT,  g_KhT);
    cudaGetSymbolAddress((void**)&pVh,   g_Vh);
    cudaGetSymbolAddress((void**)&pQh,   g_Qh);
    cudaGetSymbolAddress((void**)&pS,    g_S);
    cudaGetSymbolAddress((void**)&pCtxT, g_ctxT);
    cudaGetSymbolAddress((void**)&pPart, g_part);

    const int chArr[4] = {64, 128, 256, 512};
    const int chcum[4] = {0, 64, 192, 448};

    // 1) fused gather + K/V projection (Kh transposed)
    kvproj<<<dim3(4, 512), 256>>>(emb_all, Wk, Wv, pKhT, pVh);

    // 2) all Q projections, one launch, stacked output layout
    qproj_all<<<dim3(16, 2, 256), 128>>>(emb[0], emb[1], emb[2], emb[3],
                                         Wq[0], Wq[1], Wq[2], Wq[3], pQh);

    const float alpha = 1.f / sqrtf((float)KVc);

    // 3) stacked score GEMM: 256 uniform blocks, KhT read once per bh
    score_all<<<dim3(1, 4, 64), 256>>>(pQh, pKhT, pS, pPart, alpha);

    // 4) softmax (stats computed inline from partials)
    softmax_all<<<15360 / 8, 256>>>(pS, pPart);

    // 5) all ctx GEMMs, one launch (strided store into ctxT [B,N,CH])
    ctx_all<<<dim3(16, 2, 256), 128>>>(pS, pVh, pCtxT);

    // 6) output projections
    for (int sc = 0; sc < 4; sc++) {
        int CH = chArr[sc];
        float* ctxT = pCtxT + (long)Bc * Nc * chcum[sc];
        float* Osc  = out   + (long)Bc * Nc * chcum[sc];
        if (CH >= 256) {
            dim3 grid(CH / 128, (Bc * Nc) / 128);
            gemm128<false, true><<<grid, 256>>>(ctxT, Wo[sc], Osc,
                                                Bc * Nc, CH, CH, CH, CH, CH, 1.f);
        } else {
            dim3 grid(CH / 64, (Bc * Nc) / 64, 1);
            gemm64<false, false, true, false><<<grid, 128>>>(ctxT, Wo[sc], Osc,
                Bc * Nc, CH, CH, CH, CH, CH, 1, 1,
                0, 0, 0, 0, 0, 0, 1.f);
        }
    }
}

// round 15
// speedup vs baseline: 1.2434x; 1.0944x over previous
#include <cuda_runtime.h>
#include <math.h>
#include <stdint.h>

// Problem constants
#define Bc 16
#define Nc 1024
#define Hc 4
#define KVc 960
#define Dc 240            // KV/4, per-head K/V feature dim

#define SZ_BHND (Bc*Hc*Nc*Dc)   // 15,728,640

// ---------------- scratch (static device globals; no allocation) ----------
__device__ float g_KhT [SZ_BHND];           // [bh][240][1024]  (tf32-rounded, TRANSPOSED)
__device__ float g_Vh  [SZ_BHND];           // [bh][1024][240]  (tf32-rounded)
__device__ float g_Qh  [SZ_BHND];           // [bh][240][1024]: rows stacked by scale (tf32-rounded)
__device__ float g_S   [Bc*Hc*Dc*Dc];       // STACKED [bh][240][240]
__device__ float g_ctxS[SZ_BHND];           // STACKED [bh][240][1024] (tf32-rounded, coalesced)
__device__ float g_part[2048];              // [bh][y][sc][2] score partials (sum, sumsq)

// ---------------- helpers ----------------
__device__ __forceinline__ void cpasync16(uint32_t dst, const void* src, int sz) {
    asm volatile("cp.async.ca.shared.global [%0], [%1], 16, %2;\n"
                 :: "r"(dst), "l"(src), "r"(sz));
}
__device__ __forceinline__ uint32_t f2tf(float f) {
    uint32_t r; asm("cvt.rna.tf32.f32 %0, %1;" : "=r"(r) : "f"(f)); return r;
}
__device__ __forceinline__ float rndtf(float f) { return __uint_as_float(f2tf(f)); }

template<bool CVT>
__device__ __forceinline__ uint32_t ldop(float v) {
    return CVT ? f2tf(v) : __float_as_uint(v);
}
__device__ __forceinline__ void mma_tf32(float* acc, const uint32_t* a, const uint32_t* b) {
    asm volatile("mma.sync.aligned.m16n8k8.row.col.f32.tf32.tf32.f32 "
                 "{%0,%1,%2,%3}, {%4,%5,%6,%7}, {%8,%9}, {%0,%1,%2,%3};\n"
                 : "+f"(acc[0]), "+f"(acc[1]), "+f"(acc[2]), "+f"(acc[3])
                 : "r"(a[0]), "r"(a[1]), "r"(a[2]), "r"(a[3]), "r"(b[0]), "r"(b[1]));
}
__device__ __forceinline__ void ldsm4(uint32_t* r, uint32_t addr) {
    asm volatile("ldmatrix.sync.aligned.m8n8.x4.shared.b16 {%0,%1,%2,%3}, [%4];\n"
                 : "=r"(r[0]), "=r"(r[1]), "=r"(r[2]), "=r"(r[3]) : "r"(addr));
}

// =======================================================================
// Shared 64x64 GEMM body: 128 threads, BK=16, NT (B [Nn][K] K-contig).
// (scalar-fragment path, in-loop cvt as templated) — used by qproj.
// =======================================================================
template<bool CVTA, bool CVTB, bool RND>
__device__ __forceinline__
void gemm64_body(const float* __restrict__ A, const float* __restrict__ B, float* __restrict__ C,
                 int M, int Nn, int K, int lda, int ldb, int ldc,
                 int m0, int n0, float alpha)
{
    const int tid = threadIdx.x, lane = tid & 31, warp = tid >> 5;
    const int wm = warp >> 1, wn = warp & 1;
    const int g = lane >> 2, c4 = lane & 3;

    __shared__ float sA[2][64 * 20];
    __shared__ float sB[2][64 * 20];

    float acc[2][4][4] = {};

    const int ar = tid >> 1, ac = (tid & 1) * 8;

    auto fill = [&](int s, int k0) {
        const float* ap = A + (long)(m0 + ar) * lda + k0 + ac;
        int sa = (m0 + ar < M) ? 16 : 0;
        cpasync16((uint32_t)__cvta_generic_to_shared(&sA[s][ar * 20 + ac]),     ap,     sa);
        cpasync16((uint32_t)__cvta_generic_to_shared(&sA[s][ar * 20 + ac + 4]), ap + 4, sa);
        const float* bp = B + (long)(n0 + ar) * ldb + k0 + ac;
        int sb = (n0 + ar < Nn) ? 16 : 0;
        cpasync16((uint32_t)__cvta_generic_to_shared(&sB[s][ar * 20 + ac]),     bp,     sb);
        cpasync16((uint32_t)__cvta_generic_to_shared(&sB[s][ar * 20 + ac + 4]), bp + 4, sb);
    };

    const int KT = K >> 4;
    fill(0, 0);
    asm volatile("cp.async.commit_group;\n");
    for (int kt = 0; kt < KT; kt++) {
        int cur = kt & 1;
        if (kt + 1 < KT) fill(cur ^ 1, (kt + 1) << 4);
        asm volatile("cp.async.commit_group;\n");
        asm volatile("cp.async.wait_group 1;\n");
        __syncthreads();
        const float* a_s = sA[cur];
        const float* b_s = sB[cur];
        #pragma unroll
        for (int ks = 0; ks < 16; ks += 8) {
            uint32_t af[2][4], bf[4][2];
            #pragma unroll
            for (int fm = 0; fm < 2; fm++) {
                int mb = wm * 32 + fm * 16;
                af[fm][0] = ldop<CVTA>(a_s[(mb + g    ) * 20 + ks + c4]);
                af[fm][1] = ldop<CVTA>(a_s[(mb + g + 8) * 20 + ks + c4]);
                af[fm][2] = ldop<CVTA>(a_s[(mb + g    ) * 20 + ks + c4 + 4]);
                af[fm][3] = ldop<CVTA>(a_s[(mb + g + 8) * 20 + ks + c4 + 4]);
            }
            #pragma unroll
            for (int fn = 0; fn < 4; fn++) {
                int nb = wn * 32 + fn * 8 + g;
                bf[fn][0] = ldop<CVTB>(b_s[nb * 20 + ks + c4]);
                bf[fn][1] = ldop<CVTB>(b_s[nb * 20 + ks + c4 + 4]);
            }
            #pragma unroll
            for (int fm = 0; fm < 2; fm++)
                #pragma unroll
                for (int fn = 0; fn < 4; fn++)
                    mma_tf32(acc[fm][fn], af[fm], bf[fn]);
        }
        __syncthreads();
    }

    #pragma unroll
    for (int fm = 0; fm < 2; fm++) {
        int row0 = m0 + wm * 32 + fm * 16 + g;
        #pragma unroll
        for (int half = 0; half < 2; half++) {
            int r = row0 + half * 8;
            if (r >= M) continue;
            #pragma unroll
            for (int fn = 0; fn < 4; fn++) {
                int col = n0 + wn * 32 + fn * 8 + c4 * 2;
                if (col >= Nn) continue;
                float v0 = alpha * acc[fm][fn][half * 2 + 0];
                float v1 = alpha * acc[fm][fn][half * 2 + 1];
                if (RND) { v0 = rndtf(v0); v1 = rndtf(v1); }
                *(float2*)(C + (long)r * ldc + col) = make_float2(v0, v1);
            }
        }
    }
}

// All-scale Q projection: z = (sc<<6)|bh.
// Output STACKED: QhAll[bh][240][1024], rows offset by dcum = d-16. Rounded.
__global__ __launch_bounds__(128)
void qproj_all(const float* __restrict__ e1, const float* __restrict__ e2,
               const float* __restrict__ e3, const float* __restrict__ e4,
               const float* __restrict__ w1, const float* __restrict__ w2,
               const float* __restrict__ w3, const float* __restrict__ w4,
               float* __restrict__ Qh)
{
    const int z = blockIdx.z, sc = z >> 6, bh = z & 63, b = bh >> 2, h = bh & 3;
    const int d = 16 << sc, CH = d * 4;
    const int m0 = blockIdx.y * 64;
    if (m0 >= d) return;
    const float* emb = sc == 0 ? e1 : sc == 1 ? e2 : sc == 2 ? e3 : e4;
    const float* Wq  = sc == 0 ? w1 : sc == 1 ? w2 : sc == 2 ? w3 : w4;
    const float* A = Wq + (long)h * d * d;                 // [d][d]
    const float* B = emb + (long)b * 1024 * CH + h * d;    // [1024][CH]
    float*       C = Qh + (long)bh * 240 * 1024 + (long)(d - 16) * 1024;
    gemm64_body<true, true, true>(A, B, C, d, 1024, d, d, CH, 1024,
                                  m0, blockIdx.x * 64, 1.f);
}

// =======================================================================
// Fused gather + K/V projection (128x128 tile). Rounded outputs.
// Kh written TRANSPOSED: KhT[bh][c][n]; Vh written [bh][n][c].
// =======================================================================
__global__ __launch_bounds__(256)
void kvproj(const float* __restrict__ emb_all, const float* __restrict__ Wk,
            const float* __restrict__ Wv, float* __restrict__ KhT, float* __restrict__ Vh)
{
    const int m0 = blockIdx.y * 128, n0 = blockIdx.x * 128;
    const int tid = threadIdx.x, lane = tid & 31, warp = tid >> 5;
    const int wm = warp >> 1, wn = warp & 1;
    const int g = lane >> 2, c4 = lane & 3;

    __shared__ float sA[2][128 * 20];
    __shared__ float sB[2][128 * 20];

    float acc[2][8][4] = {};

    const int ar = tid >> 1, ac = (tid & 1) * 8;

    int m = m0 + ar;
    int b = m >> 12, h = (m >> 10) & 3, n = m & 1023;
    const float* abase = emb_all + ((long)(b * Nc + n)) * KVc;

    int r = n0 + ar;
    const float* bbase;
    int bsz;
    if (r < 240)      { bbase = Wk + (long)r * 240;         bsz = 16; }
    else if (r < 480) { bbase = Wv + (long)(r - 240) * 240; bsz = 16; }
    else              { bbase = Wk;                          bsz = 0; }

    auto seg = [&](int j) {
        return j < 16 ? 16 * h + j
             : j < 48 ? 64 + 32 * h + (j - 16)
             : j < 112 ? 192 + 64 * h + (j - 48)
             : 448 + 128 * h + (j - 112);
    };

    auto fill = [&](int s, int k0) {
        cpasync16((uint32_t)__cvta_generic_to_shared(&sA[s][ar * 20 + ac]),     abase + seg(k0 + ac),     16);
        cpasync16((uint32_t)__cvta_generic_to_shared(&sA[s][ar * 20 + ac + 4]), abase + seg(k0 + ac + 4), 16);
        cpasync16((uint32_t)__cvta_generic_to_shared(&sB[s][ar * 20 + ac]),     bbase + k0 + ac,          bsz);
        cpasync16((uint32_t)__cvta_generic_to_shared(&sB[s][ar * 20 + ac + 4]), bbase + k0 + ac + 4,      bsz);
    };

    const int KT = Dc >> 4;   // 15
    fill(0, 0);
    asm volatile("cp.async.commit_group;\n");
    for (int kt = 0; kt < KT; kt++) {
        int cur = kt & 1;
        if (kt + 1 < KT) fill(cur ^ 1, (kt + 1) << 4);
        asm volatile("cp.async.commit_group;\n");
        asm volatile("cp.async.wait_group 1;\n");
        __syncthreads();
        const float* a_s = sA[cur];
        const float* b_s = sB[cur];
        #pragma unroll
        for (int ks = 0; ks < 16; ks += 8) {
            uint32_t af[2][4], bf[8][2];
            #pragma unroll
            for (int fm = 0; fm < 2; fm++) {
                int mb = wm * 32 + fm * 16;
                af[fm][0] = f2tf(a_s[(mb + g    ) * 20 + ks + c4]);
                af[fm][1] = f2tf(a_s[(mb + g + 8) * 20 + ks + c4]);
                af[fm][2] = f2tf(a_s[(mb + g    ) * 20 + ks + c4 + 4]);
                af[fm][3] = f2tf(a_s[(mb + g + 8) * 20 + ks + c4 + 4]);
            }
            #pragma unroll
            for (int fn = 0; fn < 8; fn++) {
                int nb = wn * 64 + fn * 8 + g;
                bf[fn][0] = f2tf(b_s[nb * 20 + ks + c4]);
                bf[fn][1] = f2tf(b_s[nb * 20 + ks + c4 + 4]);
            }
            #pragma unroll
            for (int fm = 0; fm < 2; fm++)
                #pragma unroll
                for (int fn = 0; fn < 8; fn++)
                    mma_tf32(acc[fm][fn], af[fm], bf[fn]);
        }
        __syncthreads();
    }

    #pragma unroll
    for (int fm = 0; fm < 2; fm++) {
        int row0 = wm * 32 + fm * 16 + g;
        #pragma unroll
        for (int half = 0; half < 2; half++) {
            long rr = (long)(m0 + row0 + half * 8);
            int bh_o = (int)(rr >> 10), n_o = (int)(rr & 1023);
            #pragma unroll
            for (int fn = 0; fn < 8; fn++) {
                int col = n0 + wn * 64 + fn * 8 + c4 * 2;
                float2 v = make_float2(rndtf(acc[fm][fn][half * 2]),
                                       rndtf(acc[fm][fn][half * 2 + 1]));
                if (col < 240) {
                    float* p = KhT + ((long)bh_o * 240 + col) * 1024 + n_o;
                    p[0] = v.x; p[1024] = v.y;
                } else if (col < 480) {
                    *(float2*)(Vh + rr * 240 + col - 240) = v;
                }
            }
        }
    }
}

// =======================================================================
// Stacked score GEMM: [240,1024]x[1024,240]^T per bh; grid (1, 4, 64).
// C stored STACKED [bh][240][240] (coalesced). Per-scale stats partials.
// =======================================================================
__global__ __launch_bounds__(256)
void score_all(const float* __restrict__ Qh, const float* __restrict__ KhT,
               float* __restrict__ S, float* __restrict__ part, float alpha)
{
    const int bh = blockIdx.z;
    const int m0 = blockIdx.y * 64;

    const float* A = Qh  + (long)bh * 240 * 1024;   // [240][1024] stacked
    const float* B = KhT + (long)bh * 240 * 1024;   // [240][1024]
    float*       Cb = S  + (long)bh * 240 * 240;    // [240][240] stacked

    const int tid = threadIdx.x, lane = tid & 31, warp = tid >> 5;
    const int wm = warp >> 2, wn = warp & 3;      // 2 x 4 warps, warp tile 32 x 64
    const int g = lane >> 2, c4 = lane & 3;

    __shared__ float sA[2][64 * 20];
    __shared__ float sB[2][256 * 20];
    __shared__ float red[64];

    float acc[2][8][4] = {};

    const int lr = tid >> 2, lq = (tid & 3) * 4;

    auto fill = [&](int s, int k0) {
        cpasync16((uint32_t)__cvta_generic_to_shared(&sA[s][lr * 20 + lq]),
                  A + (long)(m0 + lr) * 1024 + k0 + lq, (m0 + lr < 240) ? 16 : 0);
        #pragma unroll
        for (int rd = 0; rd < 4; rd++) {
            int row = lr + rd * 64;
            cpasync16((uint32_t)__cvta_generic_to_shared(&sB[s][row * 20 + lq]),
                      B + (long)row * 1024 + k0 + lq, (row < 240) ? 16 : 0);
        }
    };

    const uint32_t sAb = (uint32_t)__cvta_generic_to_shared(sA);
    const uint32_t sBb = (uint32_t)__cvta_generic_to_shared(sB);
    const int a_row = wm * 32 + (lane & 15);
    const int a_kh  = (lane >> 4) * 4;
    const int b_row = wn * 64 + ((lane & 16) >> 1) + (lane & 7);
    const int b_kh  = ((lane >> 3) & 1) * 4;

    const int KT = 64;   // K = 1024, BK = 16
    fill(0, 0);
    asm volatile("cp.async.commit_group;\n");
    for (int kt = 0; kt < KT; kt++) {
        int cur = kt & 1;
        if (kt + 1 < KT) fill(cur ^ 1, (kt + 1) << 4);
        asm volatile("cp.async.commit_group;\n");
        asm volatile("cp.async.wait_group 1;\n");
        __syncthreads();
        const uint32_t aBase = sAb + (uint32_t)(cur * 64 * 20) * 4u;
        const uint32_t bBase = sBb + (uint32_t)(cur * 256 * 20) * 4u;
        #pragma unroll
        for (int ks = 0; ks < 16; ks += 8) {
            uint32_t af[2][4], bfr[16];
            #pragma unroll
            for (int fm = 0; fm < 2; fm++)
                ldsm4(af[fm], aBase + (uint32_t)((a_row + fm * 16) * 20 + ks + a_kh) * 4u);
            #pragma unroll
            for (int fp = 0; fp < 4; fp++)
                ldsm4(&bfr[fp * 4], bBase + (uint32_t)((b_row + fp * 16) * 20 + ks + b_kh) * 4u);
            #pragma unroll
            for (int fm = 0; fm < 2; fm++)
                #pragma unroll
                for (int fn = 0; fn < 8; fn++)
                    mma_tf32(acc[fm][fn], af[fm], &bfr[(fn >> 1) * 4 + (fn & 1) * 2]);
        }
        __syncthreads();
    }

    // epilogue: coalesced store to stacked S; per-scale stats buckets
    float ls[4] = {}, lss[4] = {};
    #pragma unroll
    for (int fm = 0; fm < 2; fm++) {
        int row0 = m0 + wm * 32 + fm * 16 + g;
        #pragma unroll
        for (int half = 0; half < 2; half++) {
            int r = row0 + half * 8;
            if (r >= 240) continue;
            int sc_r = (r < 16) ? 0 : (r < 48) ? 1 : (r < 112) ? 2 : 3;
            float rs = 0.f, rss = 0.f;
            #pragma unroll
            for (int fn = 0; fn < 8; fn++) {
                int col = wn * 64 + fn * 8 + c4 * 2;
                if (col >= 240) continue;
                float v0 = alpha * acc[fm][fn][half * 2];
                float v1 = alpha * acc[fm][fn][half * 2 + 1];
                *(float2*)(Cb + (long)r * 240 + col) = make_float2(v0, v1);
                rs  += v0 + v1;
                rss += v0 * v0 + v1 * v1;
            }
            #pragma unroll
            for (int s = 0; s < 4; s++) {
                ls[s]  += (sc_r == s) ? rs  : 0.f;
                lss[s] += (sc_r == s) ? rss : 0.f;
            }
        }
    }

    #pragma unroll
    for (int s = 0; s < 4; s++) {
        #pragma unroll
        for (int o = 16; o; o >>= 1) {
            ls[s]  += __shfl_xor_sync(0xffffffffu, ls[s],  o);
            lss[s] += __shfl_xor_sync(0xffffffffu, lss[s], o);
        }
    }
    if (lane == 0) {
        #pragma unroll
        for (int s = 0; s < 4; s++) {
            red[warp * 8 + s]     = ls[s];
            red[warp * 8 + 4 + s] = lss[s];
        }
    }
    __syncthreads();
    if (tid < 4) {
        float s = 0.f, ss = 0.f;
        #pragma unroll
        for (int j = 0; j < 8; j++) {
            s  += red[j * 8 + tid];
            ss += red[j * 8 + 4 + tid];
        }
        int idx = ((bh * 4 + blockIdx.y) * 4 + tid) * 2;
        part[idx]     = s;
        part[idx + 1] = ss;
    }
}

// =======================================================================
// Softmax over stacked S rows (inline stats). One warp per row.
// =======================================================================
__global__ __launch_bounds__(256)
void softmax_all(float* __restrict__ S, const float* __restrict__ part)
{
    int row = blockIdx.x * 8 + (threadIdx.x >> 5);   // 0..15359
    int l = threadIdx.x & 31;
    int bh = row / 240;
    int r  = row - bh * 240;
    int sc = (r < 16) ? 0 : (r < 48) ? 1 : (r < 112) ? 2 : 3;
    int d = 16 << sc;
    float* p = S + (long)bh * 240 * 240 + (long)r * 240;

    float s = 0.f, ss = 0.f;
    #pragma unroll
    for (int by = 0; by < 4; by++) {
        int idx = ((bh * 4 + by) * 4 + sc) * 2;
        s  += part[idx];
        ss += part[idx + 1];
    }
    float count = (float)(d * 240);
    float mean = s / count;
    float var  = ss / count - mean * mean;
    float istd = rsqrtf(var + 1e-5f);

    float v[8];
    float mx = -1e30f;
    #pragma unroll
    for (int t = 0; t < 8; t++) {
        int k = l + t * 32;
        float x = (k < 240) ? (p[k] - mean) * istd : -1e30f;
        v[t] = x; mx = fmaxf(mx, x);
    }
    #pragma unroll
    for (int o = 16; o; o >>= 1) mx = fmaxf(mx, __shfl_xor_sync(0xffffffffu, mx, o));
    float se = 0.f;
    #pragma unroll
    for (int t = 0; t < 8; t++) {
        int k = l + t * 32;
        float e = (k < 240) ? __expf(v[t] - mx) : 0.f;
        v[t] = e; se += e;
    }
    #pragma unroll
    for (int o = 16; o; o >>= 1) se += __shfl_xor_sync(0xffffffffu, se, o);
    float inv = 1.f / se;
    #pragma unroll
    for (int t = 0; t < 8; t++) {
        int k = l + t * 32;
        if (k < 240) p[k] = rndtf(v[t] * inv);
    }
}

// =======================================================================
// Stacked ctx GEMM: ctxS[bh][240][1024] = Sst[bh][240][240] x Vh[bh]^T.
// grid (16, 4, 64), 64x64 tiles, ldmatrix, coalesced rounded stores.
// =======================================================================
__global__ __launch_bounds__(128)
void ctx_all(const float* __restrict__ S, const float* __restrict__ Vh,
             float* __restrict__ ctxS)
{
    const int bh = blockIdx.z;
    const int m0 = blockIdx.y * 64, n0 = blockIdx.x * 64;

    const float* A = S    + (long)bh * 240 * 240;    // [240][240]
    const float* B = Vh   + (long)bh * 1024 * 240;   // [1024][240]
    float*       C = ctxS + (long)bh * 240 * 1024;   // [240][1024]

    const int tid = threadIdx.x, lane = tid & 31, warp = tid >> 5;
    const int wm = warp >> 1, wn = warp & 1;
    const int g = lane >> 2, c4 = lane & 3;

    __shared__ float sA[2][64 * 20];
    __shared__ float sB[2][64 * 20];

    float acc[2][4][4] = {};

    const int ar = tid >> 1, ac = (tid & 1) * 8;

    auto fill = [&](int s, int k0) {
        const float* ap = A + (long)(m0 + ar) * 240 + k0 + ac;
        int sa = (m0 + ar < 240) ? 16 : 0;
        cpasync16((uint32_t)__cvta_generic_to_shared(&sA[s][ar * 20 + ac]),     ap,     sa);
        cpasync16((uint32_t)__cvta_generic_to_shared(&sA[s][ar * 20 + ac + 4]), ap + 4, sa);
        const float* bp = B + (long)(n0 + ar) * 240 + k0 + ac;
        cpasync16((uint32_t)__cvta_generic_to_shared(&sB[s][ar * 20 + ac]),     bp,     16);
        cpasync16((uint32_t)__cvta_generic_to_shared(&sB[s][ar * 20 + ac + 4]), bp + 4, 16);
    };

    const uint32_t sAb = (uint32_t)__cvta_generic_to_shared(sA);
    const uint32_t sBb = (uint32_t)__cvta_generic_to_shared(sB);
    const int a_row = wm * 32 + (lane & 15);
    const int a_kh  = (lane >> 4) * 4;
    const int b_row = wn * 32 + ((lane & 16) >> 1) + (lane & 7);
    const int b_kh  = ((lane >> 3) & 1) * 4;

    const int KT = 15;   // K = 240
    fill(0, 0);
    asm volatile("cp.async.commit_group;\n");
    for (int kt = 0; kt < KT; kt++) {
        int cur = kt & 1;
        if (kt + 1 < KT) fill(cur ^ 1, (kt + 1) << 4);
        asm volatile("cp.async.commit_group;\n");
        asm volatile("cp.async.wait_group 1;\n");
        __syncthreads();
        const uint32_t aBase = sAb + (uint32_t)(cur * 64 * 20) * 4u;
        const uint32_t bBase = sBb + (uint32_t)(cur * 64 * 20) * 4u;
        #pragma unroll
        for (int ks = 0; ks < 16; ks += 8) {
            uint32_t af[2][4], bfr[2][4];
            #pragma unroll
            for (int fm = 0; fm < 2; fm++)
                ldsm4(af[fm], aBase + (uint32_t)((a_row + fm * 16) * 20 + ks + a_kh) * 4u);
            #pragma unroll
            for (int fp = 0; fp < 2; fp++)
                ldsm4(bfr[fp], bBase + (uint32_t)((b_row + fp * 16) * 20 + ks + b_kh) * 4u);
            #pragma unroll
            for (int fm = 0; fm < 2; fm++)
                #pragma unroll
                for (int fn = 0; fn < 4; fn++)
                    mma_tf32(acc[fm][fn], af[fm], &bfr[fn >> 1][(fn & 1) * 2]);
        }
        __syncthreads();
    }

    #pragma unroll
    for (int fm = 0; fm < 2; fm++) {
        int row0 = m0 + wm * 32 + fm * 16 + g;
        #pragma unroll
        for (int half = 0; half < 2; half++) {
            int r = row0 + half * 8;
            if (r >= 240) continue;
            #pragma unroll
            for (int fn = 0; fn < 4; fn++) {
                int col = n0 + wn * 32 + fn * 8 + c4 * 2;
                *(float2*)(C + (long)r * 1024 + col) =
                    make_float2(rndtf(acc[fm][fn][half * 2]),
                                rndtf(acc[fm][fn][half * 2 + 1]));
            }
        }
    }
}

// =======================================================================
// Output projection, 128x128 tile, A gathered from ctxS with transposed
// smem tile: sA[k][m], 16B coalesced loads, scalar fragment loads (pad 136).
// =======================================================================
__global__ __launch_bounds__(256)
void oproj128(const float* __restrict__ ctxS, const float* __restrict__ Wo,
              float* __restrict__ Out, int d)
{
    const int CH = d * 4, dcum = d - 16;
    const int m0 = blockIdx.y * 128, n0 = blockIdx.x * 128;
    const int tid = threadIdx.x, lane = tid & 31, warp = tid >> 5;
    const int wm = warp >> 1, wn = warp & 1;
    const int g = lane >> 2, c4 = lane & 3;

    __shared__ float sA[2][16 * 136];
    __shared__ float sB[2][128 * 20];

    float acc[2][8][4] = {};

    const int b = m0 >> 10, nb_ = m0 & 1023;
    const int cr = tid >> 4, coln = (tid & 15) * 8;       // A loader
    const int br = tid >> 1, bc = (tid & 1) * 8;          // B loader
    const float* bbase = Wo + (long)(n0 + br) * CH;

    auto fill = [&](int s, int k0) {
        int c = k0 + cr, h = c & 3, dd = c >> 2;
        const float* ap = ctxS + ((long)(b * 4 + h) * 240 + dcum + dd) * 1024 + nb_ + coln;
        cpasync16((uint32_t)__cvta_generic_to_shared(&sA[s][cr * 136 + coln]),     ap,     16);
        cpasync16((uint32_t)__cvta_generic_to_shared(&sA[s][cr * 136 + coln + 4]), ap + 4, 16);
        cpasync16((uint32_t)__cvta_generic_to_shared(&sB[s][br * 20 + bc]),     bbase + k0 + bc,     16);
        cpasync16((uint32_t)__cvta_generic_to_shared(&sB[s][br * 20 + bc + 4]), bbase + k0 + bc + 4, 16);
    };

    const int KT = CH >> 4;
    fill(0, 0);
    asm volatile("cp.async.commit_group;\n");
    for (int kt = 0; kt < KT; kt++) {
        int cur = kt & 1;
        if (kt + 1 < KT) fill(cur ^ 1, (kt + 1) << 4);
        asm volatile("cp.async.commit_group;\n");
        asm volatile("cp.async.wait_group 1;\n");
        __syncthreads();
        const float* a_s = sA[cur];
        const float* b_s = sB[cur];
        #pragma unroll
        for (int ks = 0; ks < 16; ks += 8) {
            uint32_t af[2][4], bf[8][2];
            #pragma unroll
            for (int fm = 0; fm < 2; fm++) {
                int mb = wm * 32 + fm * 16;
                af[fm][0] = __float_as_uint(a_s[(ks + c4    ) * 136 + mb + g]);
                af[fm][1] = __float_as_uint(a_s[(ks + c4    ) * 136 + mb + g + 8]);
                af[fm][2] = __float_as_uint(a_s[(ks + c4 + 4) * 136 + mb + g]);
                af[fm][3] = __float_as_uint(a_s[(ks + c4 + 4) * 136 + mb + g + 8]);
            }
            #pragma unroll
            for (int fn = 0; fn < 8; fn++) {
                int nb = wn * 64 + fn * 8 + g;
                bf[fn][0] = f2tf(b_s[nb * 20 + ks + c4]);
                bf[fn][1] = f2tf(b_s[nb * 20 + ks + c4 + 4]);
            }
            #pragma unroll
            for (int fm = 0; fm < 2; fm++)
                #pragma unroll
                for (int fn = 0; fn < 8; fn++)
                    mma_tf32(acc[fm][fn], af[fm], bf[fn]);
        }
        __syncthreads();
    }

    #pragma unroll
    for (int fm = 0; fm < 2; fm++) {
        int row0 = m0 + wm * 32 + fm * 16 + g;
        #pragma unroll
        for (int half = 0; half < 2; half++) {
            int r = row0 + half * 8;
            #pragma unroll
            for (int fn = 0; fn < 8; fn++) {
                int col = n0 + wn * 64 + fn * 8 + c4 * 2;
                *(float2*)(Out + (long)r * CH + col) =
                    make_float2(acc[fm][fn][half * 2], acc[fm][fn][half * 2 + 1]);
            }
        }
    }
}

// Output projection, 64x64 tile (CH 64/128), same transposed-A scheme (pad 72).
__global__ __launch_bounds__(128)
void oproj64(const float* __restrict__ ctxS, const float* __restrict__ Wo,
             float* __restrict__ Out, int d)
{
    const int CH = d * 4, dcum = d - 16;
    const int m0 = blockIdx.y * 64, n0 = blockIdx.x * 64;
    const int tid = threadIdx.x, lane = tid & 31, warp = tid >> 5;
    const int wm = warp >> 1, wn = warp & 1;
    const int g = lane >> 2, c4 = lane & 3;

    __shared__ float sA[2][16 * 72];
    __shared__ float sB[2][64 * 20];

    float acc[2][4][4] = {};

    const int b = m0 >> 10, nb_ = m0 & 1023;
    const int cr = tid >> 3, coln = (tid & 7) * 8;
    const int br = tid >> 1, bc = (tid & 1) * 8;
    const float* bbase = Wo + (long)(n0 + br) * CH;

    auto fill = [&](int s, int k0) {
        int c = k0 + cr, h = c & 3, dd = c >> 2;
        const float* ap = ctxS + ((long)(b * 4 + h) * 240 + dcum + dd) * 1024 + nb_ + coln;
        cpasync16((uint32_t)__cvta_generic_to_shared(&sA[s][cr * 72 + coln]),     ap,     16);
        cpasync16((uint32_t)__cvta_generic_to_shared(&sA[s][cr * 72 + coln + 4]), ap + 4, 16);
        cpasync16((uint32_t)__cvta_generic_to_shared(&sB[s][br * 20 + bc]),     bbase + k0 + bc,     16);
        cpasync16((uint32_t)__cvta_generic_to_shared(&sB[s][br * 20 + bc + 4]), bbase + k0 + bc + 4, 16);
    };

    const int KT = CH >> 4;
    fill(0, 0);
    asm volatile("cp.async.commit_group;\n");
    for (int kt = 0; kt < KT; kt++) {
        int cur = kt & 1;
        if (kt + 1 < KT) fill(cur ^ 1, (kt + 1) << 4);
        asm volatile("cp.async.commit_group;\n");
        asm volatile("cp.async.wait_group 1;\n");
        __syncthreads();
        const float* a_s = sA[cur];
        const float* b_s = sB[cur];
        #pragma unroll
        for (int ks = 0; ks < 16; ks += 8) {
            uint32_t af[2][4], bf[4][2];
            #pragma unroll
            for (int fm = 0; fm < 2; fm++) {
                int mb = wm * 32 + fm * 16;
                af[fm][0] = __float_as_uint(a_s[(ks + c4    ) * 72 + mb + g]);
                af[fm][1] = __float_as_uint(a_s[(ks + c4    ) * 72 + mb + g + 8]);
                af[fm][2] = __float_as_uint(a_s[(ks + c4 + 4) * 72 + mb + g]);
                af[fm][3] = __float_as_uint(a_s[(ks + c4 + 4) * 72 + mb + g + 8]);
            }
            #pragma unroll
            for (int fn = 0; fn < 4; fn++) {
                int nb = wn * 32 + fn * 8 + g;
                bf[fn][0] = f2tf(b_s[nb * 20 + ks + c4]);
                bf[fn][1] = f2tf(b_s[nb * 20 + ks + c4 + 4]);
            }
            #pragma unroll
            for (int fm = 0; fm < 2; fm++)
                #pragma unroll
                for (int fn = 0; fn < 4; fn++)
                    mma_tf32(acc[fm][fn], af[fm], bf[fn]);
        }
        __syncthreads();
    }

    #pragma unroll
    for (int fm = 0; fm < 2; fm++) {
        int row0 = m0 + wm * 32 + fm * 16 + g;
        #pragma unroll
        for (int half = 0; half < 2; half++) {
            int r = row0 + half * 8;
            #pragma unroll
            for (int fn = 0; fn < 4; fn++) {
                int col = n0 + wn * 32 + fn * 8 + c4 * 2;
                *(float2*)(Out + (long)r * CH + col) =
                    make_float2(acc[fm][fn][half * 2], acc[fm][fn][half * 2 + 1]);
            }
        }
    }
}

extern "C" void kernel_launch(void* const* d_in, const int* in_sizes, int n_in,
                              void* d_out, int out_size)
{
    const float* emb[4]  = { (const float*)d_in[0], (const float*)d_in[1],
                             (const float*)d_in[2], (const float*)d_in[3] };
    const float* emb_all = (const float*)d_in[4];
    const float* Wq[4]   = { (const float*)d_in[5], (const float*)d_in[6],
                             (const float*)d_in[7], (const float*)d_in[8] };
    const float* Wk      = (const float*)d_in[9];
    const float* Wv      = (const float*)d_in[10];
    const float* Wo[4]   = { (const float*)d_in[11], (const float*)d_in[12],
                             (const float*)d_in[13], (const float*)d_in[14] };
    float* out = (float*)d_out;

    float *pKhT, *pVh, *pQh, *pS, *pCtxS, *pPart;
    cudaGetSymbolAddress((void**)&pKhT,  g_KhT);
    cudaGetSymbolAddress((void**)&pVh,   g_Vh);
    cudaGetSymbolAddress((void**)&pQh,   g_Qh);
    cudaGetSymbolAddress((void**)&pS,    g_S);
    cudaGetSymbolAddress((void**)&pCtxS, g_ctxS);
    cudaGetSymbolAddress((void**)&pPart, g_part);

    // 1) fused gather + K/V projection (Kh transposed)
    kvproj<<<dim3(4, 512), 256>>>(emb_all, Wk, Wv, pKhT, pVh);

    // 2) all Q projections, one launch, stacked output layout
    qproj_all<<<dim3(16, 2, 256), 128>>>(emb[0], emb[1], emb[2], emb[3],
                                         Wq[0], Wq[1], Wq[2], Wq[3], pQh);

    const float alpha = 1.f / sqrtf((float)KVc);

    // 3) stacked score GEMM -> stacked S
    score_all<<<dim3(1, 4, 64), 256>>>(pQh, pKhT, pS, pPart, alpha);

    // 4) softmax over stacked S (inline stats)
    softmax_all<<<1920, 256>>>(pS, pPart);

    // 5) stacked ctx GEMM -> ctxS [bh][240][1024], coalesced
    ctx_all<<<dim3(16, 4, 64), 128>>>(pS, pVh, pCtxS);

    // 6) output projections (transposed-A gather from ctxS)
    const int chcum[4] = {0, 64, 192, 448};
    oproj64 <<<dim3(1, 256), 128>>>(pCtxS, Wo[0], out + 16384L * chcum[0], 16);
    oproj64 <<<dim3(2, 256), 128>>>(pCtxS, Wo[1], out + 16384L * chcum[1], 32);
    oproj128<<<dim3(2, 128), 256>>>(pCtxS, Wo[2], out + 16384L * chcum[2], 64);
    oproj128<<<dim3(4, 128), 256>>>(pCtxS, Wo[3], out + 16384L * chcum[3], 128);
}